// round 1
// baseline (speedup 1.0000x reference)
#include <cuda_runtime.h>

#define NN 50000
#define NP 800000   // undirected pairs
#define NE 1600000  // directed edges

// ---------------- scratch (static device globals; no allocations) ----------------
__device__ float  g_x1[NN * 64];
__device__ float  g_x2[NN * 64];
__device__ float  g_agg[NN * 64];
__device__ int    g_cnt[NN];
__device__ float  g_fe1[102400000];   // 800000 x 128
__device__ double g_loss[2];

// ---------------- shared memory layout (floats) ----------------
// A_T : 16 x 64      [0    .. 1024)
// W_S : 16 x 128     [1024 .. 3072)
// H_S : 64 x 132     [3072 .. 11520)
// SP  : 32 ints      [11520.. 11552)
// DP  : 32 ints      [11552.. 11584)
// RED : 32           [11584.. 11616)
#define SMEM_FLOATS 11616

__device__ __forceinline__ void block_reduce_to(double* target, float v, float* RED, int tid)
{
#pragma unroll
    for (int o = 16; o > 0; o >>= 1) v += __shfl_down_sync(0xffffffffu, v, o);
    if ((tid & 31) == 0) RED[tid >> 5] = v;
    __syncthreads();
    if (tid == 0) {
        float t = 0.f;
#pragma unroll
        for (int w = 0; w < 8; w++) t += RED[w];
        atomicAdd(target, (double)t);
    }
}

// Computes H = lrelu([x_s|x_d ; x_d|x_s] @ W0 + b0) for 32 pairs -> H_S[64][132]
__device__ __forceinline__ void mlp_hidden(
    const float* __restrict__ x,
    const float* __restrict__ W0,
    const float* __restrict__ b0,
    float* A_T, float* W_S, float* H_S,
    const int* SP, const int* DP, int tid)
{
    const int tr = tid >> 4, tc = tid & 15;     // 16x16 thread grid: rows tr*4.., cols tc*8..
    const int rA = tid >> 2, qA = tid & 3;      // gather: row rA, float4 chunk qA
    const int pA = rA >> 1, vA = rA & 1;
    const int sN = SP[pA], dN = DP[pA];
    const float4* x4 = (const float4*)x;

    float acc[4][8];
#pragma unroll
    for (int i = 0; i < 4; i++)
#pragma unroll
        for (int j = 0; j < 8; j++) acc[i][j] = 0.f;

    for (int kc = 0; kc < 128; kc += 16) {
        // gather A chunk (transposed: A_T[k][r]) ; variant v=0:[x_s|x_d], v=1:[x_d|x_s]
        int half = (kc >> 6) & 1;
        int n = (half == vA) ? sN : dN;
        float4 av = x4[n * 16 + ((kc & 63) >> 2) + qA];
        A_T[(qA * 4 + 0) * 64 + rA] = av.x;
        A_T[(qA * 4 + 1) * 64 + rA] = av.y;
        A_T[(qA * 4 + 2) * 64 + rA] = av.z;
        A_T[(qA * 4 + 3) * 64 + rA] = av.w;
        // stage W0 chunk [16][128]
#pragma unroll
        for (int t = 0; t < 2; t++) {
            int idx = tid + t * 256;
            int kk = idx >> 5, n4 = idx & 31;
            *(float4*)&W_S[kk * 128 + n4 * 4] = ((const float4*)(W0 + (kc + kk) * 128))[n4];
        }
        __syncthreads();
#pragma unroll
        for (int kk = 0; kk < 16; kk++) {
            float4 a4 = *(const float4*)&A_T[kk * 64 + tr * 4];
            float4 w0 = *(const float4*)&W_S[kk * 128 + tc * 8];
            float4 w1 = *(const float4*)&W_S[kk * 128 + tc * 8 + 4];
            float a[4] = {a4.x, a4.y, a4.z, a4.w};
            float w[8] = {w0.x, w0.y, w0.z, w0.w, w1.x, w1.y, w1.z, w1.w};
#pragma unroll
            for (int i = 0; i < 4; i++)
#pragma unroll
                for (int j = 0; j < 8; j++) acc[i][j] += a[i] * w[j];
        }
        __syncthreads();
    }
    float4 ba = ((const float4*)b0)[tc * 2];
    float4 bb = ((const float4*)b0)[tc * 2 + 1];
    float bj[8] = {ba.x, ba.y, ba.z, ba.w, bb.x, bb.y, bb.z, bb.w};
#pragma unroll
    for (int i = 0; i < 4; i++) {
        float h[8];
#pragma unroll
        for (int j = 0; j < 8; j++) {
            float v = acc[i][j] + bj[j];
            h[j] = v > 0.f ? v : 0.01f * v;
        }
        *(float4*)&H_S[(tr * 4 + i) * 132 + tc * 8]     = make_float4(h[0], h[1], h[2], h[3]);
        *(float4*)&H_S[(tr * 4 + i) * 132 + tc * 8 + 4] = make_float4(h[4], h[5], h[6], h[7]);
    }
    __syncthreads();
}

// ------------------------------------------------------------------
__global__ void count_kernel(const int* __restrict__ ei, int* __restrict__ cnt)
{
    int j = blockIdx.x * blockDim.x + threadIdx.x;
    if (j < NP) {
        atomicAdd(&cnt[ei[j]], 1);
        atomicAdd(&cnt[ei[NP + j]], 1);
    }
}

__global__ void divide_kernel(const float* __restrict__ agg, const int* __restrict__ cnt,
                              float* __restrict__ x)
{
    int i = blockIdx.x * 256 + threadIdx.x;
    if (i < NN * 64) {
        float c = (float)cnt[i >> 6];
        x[i] = agg[i] / fmaxf(c, 1.0f);
    }
}

// ------------------------------------------------------------------
__global__ void __launch_bounds__(256) node_conv_kernel(
    const float* __restrict__ x, const int* __restrict__ ei,
    const float* __restrict__ W0, const float* __restrict__ b0,
    const float* __restrict__ W1, const float* __restrict__ b1,
    float* __restrict__ agg)
{
    __shared__ float sm[SMEM_FLOATS];
    float* A_T = sm;
    float* W_S = sm + 1024;
    float* H_S = sm + 3072;
    int* SP = (int*)(sm + 11520);
    int* DP = (int*)(sm + 11552);
    const int tid = threadIdx.x;
    const int pbase = blockIdx.x * 32;
    if (tid < 32) { SP[tid] = ei[pbase + tid]; DP[tid] = ei[NP + pbase + tid]; }
    __syncthreads();

    mlp_hidden(x, W0, b0, A_T, W_S, H_S, SP, DP, tid);

    // phase2: M[64,64] = H @ W1 + b1 ; scatter to agg
    float acc[4][4];
#pragma unroll
    for (int i = 0; i < 4; i++)
#pragma unroll
        for (int j = 0; j < 4; j++) acc[i][j] = 0.f;
    const int tr = tid >> 4, tc = tid & 15;
    for (int kc = 0; kc < 128; kc += 16) {
        {
            int kk = tid >> 4, n4 = tid & 15;
            *(float4*)&W_S[kk * 64 + n4 * 4] = ((const float4*)(W1 + (kc + kk) * 64))[n4];
        }
        __syncthreads();
#pragma unroll
        for (int k2 = 0; k2 < 16; k2++) {
            float h0 = H_S[(tr * 4 + 0) * 132 + kc + k2];
            float h1 = H_S[(tr * 4 + 1) * 132 + kc + k2];
            float h2 = H_S[(tr * 4 + 2) * 132 + kc + k2];
            float h3 = H_S[(tr * 4 + 3) * 132 + kc + k2];
            float4 w = *(const float4*)&W_S[k2 * 64 + tc * 4];
            acc[0][0] += h0 * w.x; acc[0][1] += h0 * w.y; acc[0][2] += h0 * w.z; acc[0][3] += h0 * w.w;
            acc[1][0] += h1 * w.x; acc[1][1] += h1 * w.y; acc[1][2] += h1 * w.z; acc[1][3] += h1 * w.w;
            acc[2][0] += h2 * w.x; acc[2][1] += h2 * w.y; acc[2][2] += h2 * w.z; acc[2][3] += h2 * w.w;
            acc[3][0] += h3 * w.x; acc[3][1] += h3 * w.y; acc[3][2] += h3 * w.z; acc[3][3] += h3 * w.w;
        }
        __syncthreads();
    }
    float4 bv = ((const float4*)b1)[tc];
    float bj[4] = {bv.x, bv.y, bv.z, bv.w};
#pragma unroll
    for (int i = 0; i < 4; i++) {
        int rr = tr * 4 + i;
        int pp = rr >> 1, vv = rr & 1;
        int node = vv ? SP[pp] : DP[pp];   // m1 (v=0) -> dst=d ; m2 (v=1) -> dst=s
        float* dst = agg + node * 64 + tc * 4;
#pragma unroll
        for (int j = 0; j < 4; j++) atomicAdd(dst + j, acc[i][j] + bj[j]);
    }
}

// ------------------------------------------------------------------
__global__ void __launch_bounds__(256) edge_conv1_kernel(
    const float* __restrict__ x, const int* __restrict__ ei,
    const float* __restrict__ act, const float* __restrict__ ang,
    const float* __restrict__ W0, const float* __restrict__ b0,
    const float* __restrict__ W1, const float* __restrict__ b1,
    const float* __restrict__ Wl, const float* __restrict__ bl,
    float* __restrict__ fe1, double* __restrict__ lossp)
{
    __shared__ float sm[SMEM_FLOATS];
    float* A_T = sm;
    float* W_S = sm + 1024;
    float* H_S = sm + 3072;
    int* SP = (int*)(sm + 11520);
    int* DP = (int*)(sm + 11552);
    float* RED = sm + 11584;
    const int tid = threadIdx.x;
    const int pbase = blockIdx.x * 32;
    if (tid < 32) { SP[tid] = ei[pbase + tid]; DP[tid] = ei[NP + pbase + tid]; }
    __syncthreads();

    mlp_hidden(x, W0, b0, A_T, W_S, H_S, SP, DP, tid);

    // phase2: M[64,128] = H @ W1 + b1
    float acc[4][8];
#pragma unroll
    for (int i = 0; i < 4; i++)
#pragma unroll
        for (int j = 0; j < 8; j++) acc[i][j] = 0.f;
    const int tr = tid >> 4, tc = tid & 15;
    for (int kc = 0; kc < 128; kc += 16) {
#pragma unroll
        for (int t = 0; t < 2; t++) {
            int idx = tid + t * 256;
            int kk = idx >> 5, n4 = idx & 31;
            *(float4*)&W_S[kk * 128 + n4 * 4] = ((const float4*)(W1 + (kc + kk) * 128))[n4];
        }
        __syncthreads();
#pragma unroll
        for (int kk = 0; kk < 16; kk++) {
            float h[4];
#pragma unroll
            for (int i = 0; i < 4; i++) h[i] = H_S[(tr * 4 + i) * 132 + kc + kk];
            float4 w0 = *(const float4*)&W_S[kk * 128 + tc * 8];
            float4 w1 = *(const float4*)&W_S[kk * 128 + tc * 8 + 4];
            float w[8] = {w0.x, w0.y, w0.z, w0.w, w1.x, w1.y, w1.z, w1.w};
#pragma unroll
            for (int i = 0; i < 4; i++)
#pragma unroll
                for (int j = 0; j < 8; j++) acc[i][j] += h[i] * w[j];
        }
        __syncthreads();
    }
    {
        float4 ba = ((const float4*)b1)[tc * 2];
        float4 bb = ((const float4*)b1)[tc * 2 + 1];
        float bj[8] = {ba.x, ba.y, ba.z, ba.w, bb.x, bb.y, bb.z, bb.w};
#pragma unroll
        for (int i = 0; i < 4; i++)
#pragma unroll
            for (int j = 0; j < 8; j++) acc[i][j] += bj[j];
    }
    // combine pairs -> Fe (rows 0..31 of H_S region), accumulate side-loss
    float lsum = 0.f;
#pragma unroll
    for (int pi = 0; pi < 2; pi++) {
        int p = tr * 2 + pi;
        float fe[8];
#pragma unroll
        for (int j = 0; j < 8; j++) {
            float m1 = acc[2 * pi][j], m2 = acc[2 * pi + 1][j];
            float df = m1 - m2; lsum += df * df;
            fe[j] = 0.5f * (m1 + m2);
        }
        *(float4*)&H_S[p * 132 + tc * 8]     = make_float4(fe[0], fe[1], fe[2], fe[3]);
        *(float4*)&H_S[p * 132 + tc * 8 + 4] = make_float4(fe[4], fe[5], fe[6], fe[7]);
    }
    if (tid < 32) {
        H_S[tid * 132 + 128] = act[pbase + tid];   // actions first
        H_S[tid * 132 + 129] = ang[pbase + tid];   // then angles
    }
    block_reduce_to(lossp, lsum, RED, tid);
    __syncthreads();

    // phase3: out[32,128] = [fe|act|ang] @ Wl[130,128] + bl
    float acc3[4][4];
#pragma unroll
    for (int i = 0; i < 4; i++)
#pragma unroll
        for (int j = 0; j < 4; j++) acc3[i][j] = 0.f;
    const int tr3 = tid >> 5, tc3 = tid & 31;
    for (int kc = 0; kc < 130; kc += 16) {
        int klen = (130 - kc) < 16 ? (130 - kc) : 16;
#pragma unroll
        for (int t = 0; t < 2; t++) {
            int idx = tid + t * 256;
            int kk = idx >> 5, n4 = idx & 31;
            if (kk < klen)
                *(float4*)&W_S[kk * 128 + n4 * 4] = ((const float4*)(Wl + (kc + kk) * 128))[n4];
        }
        __syncthreads();
        if (klen == 16) {
#pragma unroll
            for (int kk = 0; kk < 16; kk++) {
                float f0 = H_S[(tr3 * 4 + 0) * 132 + kc + kk];
                float f1 = H_S[(tr3 * 4 + 1) * 132 + kc + kk];
                float f2 = H_S[(tr3 * 4 + 2) * 132 + kc + kk];
                float f3 = H_S[(tr3 * 4 + 3) * 132 + kc + kk];
                float4 w = *(const float4*)&W_S[kk * 128 + tc3 * 4];
                acc3[0][0] += f0 * w.x; acc3[0][1] += f0 * w.y; acc3[0][2] += f0 * w.z; acc3[0][3] += f0 * w.w;
                acc3[1][0] += f1 * w.x; acc3[1][1] += f1 * w.y; acc3[1][2] += f1 * w.z; acc3[1][3] += f1 * w.w;
                acc3[2][0] += f2 * w.x; acc3[2][1] += f2 * w.y; acc3[2][2] += f2 * w.z; acc3[2][3] += f2 * w.w;
                acc3[3][0] += f3 * w.x; acc3[3][1] += f3 * w.y; acc3[3][2] += f3 * w.z; acc3[3][3] += f3 * w.w;
            }
        } else {
#pragma unroll
            for (int kk = 0; kk < 2; kk++) {
                float f0 = H_S[(tr3 * 4 + 0) * 132 + kc + kk];
                float f1 = H_S[(tr3 * 4 + 1) * 132 + kc + kk];
                float f2 = H_S[(tr3 * 4 + 2) * 132 + kc + kk];
                float f3 = H_S[(tr3 * 4 + 3) * 132 + kc + kk];
                float4 w = *(const float4*)&W_S[kk * 128 + tc3 * 4];
                acc3[0][0] += f0 * w.x; acc3[0][1] += f0 * w.y; acc3[0][2] += f0 * w.z; acc3[0][3] += f0 * w.w;
                acc3[1][0] += f1 * w.x; acc3[1][1] += f1 * w.y; acc3[1][2] += f1 * w.z; acc3[1][3] += f1 * w.w;
                acc3[2][0] += f2 * w.x; acc3[2][1] += f2 * w.y; acc3[2][2] += f2 * w.z; acc3[2][3] += f2 * w.w;
                acc3[3][0] += f3 * w.x; acc3[3][1] += f3 * w.y; acc3[3][2] += f3 * w.z; acc3[3][3] += f3 * w.w;
            }
        }
        __syncthreads();
    }
    float4 blv = ((const float4*)bl)[tc3];
#pragma unroll
    for (int i = 0; i < 4; i++) {
        int p = tr3 * 4 + i;
        *(float4*)&fe1[(size_t)(pbase + p) * 128 + tc3 * 4] =
            make_float4(acc3[i][0] + blv.x, acc3[i][1] + blv.y, acc3[i][2] + blv.z, acc3[i][3] + blv.w);
    }
}

// ------------------------------------------------------------------
__global__ void __launch_bounds__(256) edge_conv2_kernel(
    const float* __restrict__ x, const int* __restrict__ ei,
    const float* __restrict__ fe1,
    const float* __restrict__ W0, const float* __restrict__ b0,
    const float* __restrict__ W1, const float* __restrict__ b1,
    const float* __restrict__ Wl, const float* __restrict__ bl,
    float* __restrict__ out, double* __restrict__ lossp)
{
    __shared__ float sm[SMEM_FLOATS];
    float* A_T = sm;
    float* W_S = sm + 1024;
    float* H_S = sm + 3072;
    int* SP = (int*)(sm + 11520);
    int* DP = (int*)(sm + 11552);
    float* RED = sm + 11584;
    // small regions reusing W_S after phase1:
    float* W1S = W_S;          // 384 floats (128x3)
    float* M_S = W_S + 384;    // 192 floats (64x3)
    float* FE2 = W_S + 576;    // 96 floats  (32x3)
    float* WL2 = W_S + 672;    // 393 floats (131x3)
    const int tid = threadIdx.x;
    const int pbase = blockIdx.x * 32;
    if (tid < 32) { SP[tid] = ei[pbase + tid]; DP[tid] = ei[NP + pbase + tid]; }
    __syncthreads();

    mlp_hidden(x, W0, b0, A_T, W_S, H_S, SP, DP, tid);

    // stage W1 (128x3)
    if (tid < 96) ((float4*)W1S)[tid] = ((const float4*)W1)[tid];
    __syncthreads();
    // M[64,3] = H @ W1 + b1
    if (tid < 192) {
        int r = tid & 63, c = tid >> 6;
        float s = b1[c];
#pragma unroll 4
        for (int k = 0; k < 128; k++) s += H_S[r * 132 + k] * W1S[k * 3 + c];
        M_S[r * 3 + c] = s;
    }
    __syncthreads();

    float lsum = 0.f;
    if (tid < 96) {
        int p = tid & 31, c = tid >> 5;
        float m1 = M_S[(2 * p) * 3 + c], m2 = M_S[(2 * p + 1) * 3 + c];
        float df = m1 - m2; lsum = df * df;
        FE2[p * 3 + c] = 0.5f * (m1 + m2);
    }
    // stage Wl (131x3)
    for (int i = tid; i < 393; i += 256) WL2[i] = Wl[i];
    // load fe1 rows into H_S (stride 132) — H_S reads done (synced above)
#pragma unroll
    for (int t = 0; t < 4; t++) {
        int idx = tid + t * 256;
        int pr = idx >> 5, c4 = idx & 31;
        *(float4*)&H_S[pr * 132 + c4 * 4] =
            ((const float4*)&fe1[(size_t)(pbase + pr) * 128])[c4];
    }
    block_reduce_to(lossp, lsum, RED, tid);
    __syncthreads();

    // out[32,3] = [fe2(3) | fe1(128)] @ Wl[131,3] + bl
    if (tid < 96) {
        int p = tid & 31, c = tid >> 5;
        float s = bl[c];
#pragma unroll
        for (int k = 0; k < 3; k++) s += FE2[p * 3 + k] * WL2[k * 3 + c];
#pragma unroll 4
        for (int k = 0; k < 128; k++) s += H_S[p * 132 + k] * WL2[(3 + k) * 3 + c];
        out[(size_t)(pbase + p) * 3 + c] = s;
    }
}

// ------------------------------------------------------------------
__global__ void finalize_kernel(float* __restrict__ out, int idx)
{
    double l = 0.5 * (g_loss[0] / (800000.0 * 128.0) + g_loss[1] / (800000.0 * 3.0));
    out[idx] = (float)l;
}

// ------------------------------------------------------------------
extern "C" void kernel_launch(void* const* d_in, const int* in_sizes, int n_in,
                              void* d_out, int out_size)
{
    (void)in_sizes; (void)n_in;
    const float* xnf  = (const float*)d_in[0];
    const int*   ei   = (const int*)d_in[1];
    const float* ang  = (const float*)d_in[2];
    const float* act  = (const float*)d_in[3];
    const float* nc1W0 = (const float*)d_in[5];
    const float* nc1b0 = (const float*)d_in[6];
    const float* nc1W1 = (const float*)d_in[7];
    const float* nc1b1 = (const float*)d_in[8];
    const float* ec1W0 = (const float*)d_in[9];
    const float* ec1b0 = (const float*)d_in[10];
    const float* ec1W1 = (const float*)d_in[11];
    const float* ec1b1 = (const float*)d_in[12];
    const float* ec1Wl = (const float*)d_in[13];
    const float* ec1bl = (const float*)d_in[14];
    const float* nc2W0 = (const float*)d_in[15];
    const float* nc2b0 = (const float*)d_in[16];
    const float* nc2W1 = (const float*)d_in[17];
    const float* nc2b1 = (const float*)d_in[18];
    const float* ec2W0 = (const float*)d_in[19];
    const float* ec2b0 = (const float*)d_in[20];
    const float* ec2W1 = (const float*)d_in[21];
    const float* ec2b1 = (const float*)d_in[22];
    const float* ec2Wl = (const float*)d_in[23];
    const float* ec2bl = (const float*)d_in[24];
    float* out = (float*)d_out;

    float *agg, *x1, *x2, *fe1;
    int* cnt;
    double* loss;
    cudaGetSymbolAddress((void**)&agg,  g_agg);
    cudaGetSymbolAddress((void**)&x1,   g_x1);
    cudaGetSymbolAddress((void**)&x2,   g_x2);
    cudaGetSymbolAddress((void**)&fe1,  g_fe1);
    cudaGetSymbolAddress((void**)&cnt,  g_cnt);
    cudaGetSymbolAddress((void**)&loss, g_loss);

    cudaMemsetAsync(agg, 0, (size_t)NN * 64 * sizeof(float));
    cudaMemsetAsync(cnt, 0, (size_t)NN * sizeof(int));
    cudaMemsetAsync(loss, 0, 2 * sizeof(double));

    count_kernel<<<(NP + 255) / 256, 256>>>(ei, cnt);
    node_conv_kernel<<<NP / 32, 256>>>(xnf, ei, nc1W0, nc1b0, nc1W1, nc1b1, agg);
    divide_kernel<<<(NN * 64 + 255) / 256, 256>>>(agg, cnt, x1);
    cudaMemsetAsync(agg, 0, (size_t)NN * 64 * sizeof(float));
    edge_conv1_kernel<<<NP / 32, 256>>>(x1, ei, act, ang,
                                        ec1W0, ec1b0, ec1W1, ec1b1, ec1Wl, ec1bl,
                                        fe1, loss);
    node_conv_kernel<<<NP / 32, 256>>>(x1, ei, nc2W0, nc2b0, nc2W1, nc2b1, agg);
    divide_kernel<<<(NN * 64 + 255) / 256, 256>>>(agg, cnt, x2);
    edge_conv2_kernel<<<NP / 32, 256>>>(x2, ei, fe1,
                                        ec2W0, ec2b0, ec2W1, ec2b1, ec2Wl, ec2bl,
                                        out, loss + 1);
    finalize_kernel<<<1, 1>>>(out, out_size - 1);
}

// round 2
// speedup vs baseline: 2.1649x; 2.1649x over previous
#include <cuda_runtime.h>

#define NN 50000
#define NP 800000   // undirected pairs

// ---------------- scratch (static device globals; no allocations) ----------------
__device__ float  g_x1[NN * 64];
__device__ float  g_x2[NN * 64];
__device__ float  g_agg[NN * 64];
__device__ int    g_cnt[NN];
__device__ float  g_PA[NN * 256];
__device__ float  g_PB[NN * 256];
__device__ float  g_fe1[102400000];   // 800000 x 128
__device__ double g_loss[2];

// ---------------- shared memory layout for edge kernels (floats) ----------------
// W_S : 2048          [0     .. 2048)   (b0 staged in [0..128) during H build)
// H_S : 64 x 132      [2048  .. 10496)
// SP  : 32 ints       [10496 .. 10528)
// DP  : 32 ints       [10528 .. 10560)
// RED : 32            [10560 .. 10592)
#define SMEM_FLOATS 10592

__device__ __forceinline__ void block_reduce_to(double* target, float v, float* RED, int tid)
{
#pragma unroll
    for (int o = 16; o > 0; o >>= 1) v += __shfl_down_sync(0xffffffffu, v, o);
    if ((tid & 31) == 0) RED[tid >> 5] = v;
    __syncthreads();
    if (tid == 0) {
        float t = 0.f;
#pragma unroll
        for (int w = 0; w < 8; w++) t += RED[w];
        atomicAdd(target, (double)t);
    }
}

// H[64][132] = lrelu(Pt[a] + Pb[b] + b0), rows: pair p, v=0 -> (s,d), v=1 -> (d,s)
__device__ __forceinline__ void build_H(
    const float* __restrict__ P, const float* b0s, float* H_S,
    const int* SP, const int* DP, int tid)
{
#pragma unroll
    for (int it = 0; it < 8; it++) {
        int idx = tid + it * 256;
        int r = idx >> 5, c4 = idx & 31;
        int pp = r >> 1, v = r & 1;
        int na = v ? DP[pp] : SP[pp];
        int nb = v ? SP[pp] : DP[pp];
        float4 a = __ldg((const float4*)(P + (size_t)na * 256) + c4);        // Pt
        float4 b = __ldg((const float4*)(P + (size_t)nb * 256) + 32 + c4);   // Pb
        float bx = b0s[c4 * 4], by = b0s[c4 * 4 + 1], bz = b0s[c4 * 4 + 2], bw = b0s[c4 * 4 + 3];
        float4 h; float z;
        z = a.x + b.x + bx; h.x = z > 0.f ? z : 0.01f * z;
        z = a.y + b.y + by; h.y = z > 0.f ? z : 0.01f * z;
        z = a.z + b.z + bz; h.z = z > 0.f ? z : 0.01f * z;
        z = a.w + b.w + bw; h.w = z > 0.f ? z : 0.01f * z;
        *(float4*)&H_S[r * 132 + c4 * 4] = h;
    }
}

// ------------------------------------------------------------------
// P[n][0..127] = x[n] @ W0[0:64,:]  ; P[n][128..255] = x[n] @ W0[64:128,:]
__global__ void __launch_bounds__(256) node_proj_kernel(
    const float* __restrict__ x, const float* __restrict__ W0, float* __restrict__ P)
{
    __shared__ float XT[64 * 68];
    __shared__ float WC[16 * 256];
    const int tid = threadIdx.x;
    const int nbase = blockIdx.x * 64;
    // stage XT[k][r] (transposed x tile)
#pragma unroll
    for (int i = 0; i < 4; i++) {
        int lin = tid * 4 + i;           // 0..1023
        int r = lin >> 4, q = lin & 15;
        int node = nbase + r; if (node >= NN) node = NN - 1;
        float4 v = __ldg((const float4*)x + (size_t)node * 16 + q);
        XT[(q * 4 + 0) * 68 + r] = v.x;
        XT[(q * 4 + 1) * 68 + r] = v.y;
        XT[(q * 4 + 2) * 68 + r] = v.z;
        XT[(q * 4 + 3) * 68 + r] = v.w;
    }
    float acc[8][8];
#pragma unroll
    for (int i = 0; i < 8; i++)
#pragma unroll
        for (int j = 0; j < 8; j++) acc[i][j] = 0.f;
    const int tr = tid >> 5, tc = tid & 31;
    for (int kc = 0; kc < 64; kc += 16) {
        __syncthreads();
        // stage WC[kk][j]: j<128 from W0[kc+kk], j>=128 from W0[64+kc+kk]
#pragma unroll
        for (int i = 0; i < 4; i++) {
            int lin = tid + i * 256;          // float4 index 0..1023
            int kk = lin >> 6, j4 = lin & 63;
            int j = j4 * 4;
            const float* src = (j < 128) ? (W0 + (kc + kk) * 128 + j)
                                         : (W0 + (64 + kc + kk) * 128 + (j - 128));
            *(float4*)&WC[kk * 256 + j] = *(const float4*)src;
        }
        __syncthreads();
#pragma unroll
        for (int kk = 0; kk < 16; kk++) {
            float4 a0 = *(const float4*)&XT[(kc + kk) * 68 + tr * 8];
            float4 a1 = *(const float4*)&XT[(kc + kk) * 68 + tr * 8 + 4];
            float4 w0 = *(const float4*)&WC[kk * 256 + tc * 8];
            float4 w1 = *(const float4*)&WC[kk * 256 + tc * 8 + 4];
            float a[8] = {a0.x, a0.y, a0.z, a0.w, a1.x, a1.y, a1.z, a1.w};
            float w[8] = {w0.x, w0.y, w0.z, w0.w, w1.x, w1.y, w1.z, w1.w};
#pragma unroll
            for (int i = 0; i < 8; i++)
#pragma unroll
                for (int j = 0; j < 8; j++) acc[i][j] += a[i] * w[j];
        }
    }
#pragma unroll
    for (int i = 0; i < 8; i++) {
        int node = nbase + tr * 8 + i;
        if (node < NN) {
            *(float4*)&P[(size_t)node * 256 + tc * 8] =
                make_float4(acc[i][0], acc[i][1], acc[i][2], acc[i][3]);
            *(float4*)&P[(size_t)node * 256 + tc * 8 + 4] =
                make_float4(acc[i][4], acc[i][5], acc[i][6], acc[i][7]);
        }
    }
}

// ------------------------------------------------------------------
__global__ void count_kernel(const int* __restrict__ ei, int* __restrict__ cnt)
{
    int j = blockIdx.x * blockDim.x + threadIdx.x;
    if (j < NP) {
        atomicAdd(&cnt[ei[j]], 1);
        atomicAdd(&cnt[ei[NP + j]], 1);
    }
}

__global__ void divide_kernel(const float* __restrict__ agg, const int* __restrict__ cnt,
                              float* __restrict__ x)
{
    int i = blockIdx.x * 256 + threadIdx.x;
    if (i < NN * 64) {
        float c = (float)cnt[i >> 6];
        x[i] = agg[i] / fmaxf(c, 1.0f);
    }
}

// ------------------------------------------------------------------
__global__ void __launch_bounds__(256) node_conv_kernel(
    const float* __restrict__ P, const int* __restrict__ ei,
    const float* __restrict__ b0,
    const float* __restrict__ W1, const float* __restrict__ b1,
    float* __restrict__ agg)
{
    __shared__ float sm[SMEM_FLOATS];
    float* W_S = sm;
    float* H_S = sm + 2048;
    int* SP = (int*)(sm + 10496);
    int* DP = (int*)(sm + 10528);
    const int tid = threadIdx.x;
    const int pbase = blockIdx.x * 32;
    if (tid < 32) {
        SP[tid] = ei[pbase + tid];
        DP[tid] = ei[NP + pbase + tid];
        ((float4*)W_S)[tid] = ((const float4*)b0)[tid];
    }
    __syncthreads();
    build_H(P, W_S, H_S, SP, DP, tid);
    __syncthreads();

    // M[64,64] = H @ W1 + b1 ; scatter to agg
    float acc[4][4];
#pragma unroll
    for (int i = 0; i < 4; i++)
#pragma unroll
        for (int j = 0; j < 4; j++) acc[i][j] = 0.f;
    const int tr = tid >> 4, tc = tid & 15;
    for (int kc = 0; kc < 128; kc += 16) {
        {
            int kk = tid >> 4, n4 = tid & 15;
            *(float4*)&W_S[kk * 64 + n4 * 4] = ((const float4*)(W1 + (kc + kk) * 64))[n4];
        }
        __syncthreads();
#pragma unroll
        for (int k2 = 0; k2 < 16; k2++) {
            float h0 = H_S[(tr * 4 + 0) * 132 + kc + k2];
            float h1 = H_S[(tr * 4 + 1) * 132 + kc + k2];
            float h2 = H_S[(tr * 4 + 2) * 132 + kc + k2];
            float h3 = H_S[(tr * 4 + 3) * 132 + kc + k2];
            float4 w = *(const float4*)&W_S[k2 * 64 + tc * 4];
            acc[0][0] += h0 * w.x; acc[0][1] += h0 * w.y; acc[0][2] += h0 * w.z; acc[0][3] += h0 * w.w;
            acc[1][0] += h1 * w.x; acc[1][1] += h1 * w.y; acc[1][2] += h1 * w.z; acc[1][3] += h1 * w.w;
            acc[2][0] += h2 * w.x; acc[2][1] += h2 * w.y; acc[2][2] += h2 * w.z; acc[2][3] += h2 * w.w;
            acc[3][0] += h3 * w.x; acc[3][1] += h3 * w.y; acc[3][2] += h3 * w.z; acc[3][3] += h3 * w.w;
        }
        __syncthreads();
    }
    float4 bv = ((const float4*)b1)[tc];
    float bj[4] = {bv.x, bv.y, bv.z, bv.w};
#pragma unroll
    for (int i = 0; i < 4; i++) {
        int rr = tr * 4 + i;
        int pp = rr >> 1, vv = rr & 1;
        int node = vv ? SP[pp] : DP[pp];   // m1 (v=0) -> dst=d ; m2 (v=1) -> dst=s
        float* dst = agg + node * 64 + tc * 4;
#pragma unroll
        for (int j = 0; j < 4; j++) atomicAdd(dst + j, acc[i][j] + bj[j]);
    }
}

// ------------------------------------------------------------------
__global__ void __launch_bounds__(256) edge_conv1_kernel(
    const float* __restrict__ P, const int* __restrict__ ei,
    const float* __restrict__ act, const float* __restrict__ ang,
    const float* __restrict__ b0,
    const float* __restrict__ W1, const float* __restrict__ b1,
    const float* __restrict__ Wl, const float* __restrict__ bl,
    float* __restrict__ fe1, double* __restrict__ lossp)
{
    __shared__ float sm[SMEM_FLOATS];
    float* W_S = sm;
    float* H_S = sm + 2048;
    int* SP = (int*)(sm + 10496);
    int* DP = (int*)(sm + 10528);
    float* RED = sm + 10560;
    const int tid = threadIdx.x;
    const int pbase = blockIdx.x * 32;
    if (tid < 32) {
        SP[tid] = ei[pbase + tid];
        DP[tid] = ei[NP + pbase + tid];
        ((float4*)W_S)[tid] = ((const float4*)b0)[tid];
    }
    __syncthreads();
    build_H(P, W_S, H_S, SP, DP, tid);
    __syncthreads();

    // M[64,128] = H @ W1 + b1
    float acc[4][8];
#pragma unroll
    for (int i = 0; i < 4; i++)
#pragma unroll
        for (int j = 0; j < 8; j++) acc[i][j] = 0.f;
    const int tr = tid >> 4, tc = tid & 15;
    for (int kc = 0; kc < 128; kc += 16) {
#pragma unroll
        for (int t = 0; t < 2; t++) {
            int idx = tid + t * 256;
            int kk = idx >> 5, n4 = idx & 31;
            *(float4*)&W_S[kk * 128 + n4 * 4] = ((const float4*)(W1 + (kc + kk) * 128))[n4];
        }
        __syncthreads();
#pragma unroll
        for (int kk = 0; kk < 16; kk++) {
            float h[4];
#pragma unroll
            for (int i = 0; i < 4; i++) h[i] = H_S[(tr * 4 + i) * 132 + kc + kk];
            float4 w0 = *(const float4*)&W_S[kk * 128 + tc * 8];
            float4 w1 = *(const float4*)&W_S[kk * 128 + tc * 8 + 4];
            float w[8] = {w0.x, w0.y, w0.z, w0.w, w1.x, w1.y, w1.z, w1.w};
#pragma unroll
            for (int i = 0; i < 4; i++)
#pragma unroll
                for (int j = 0; j < 8; j++) acc[i][j] += h[i] * w[j];
        }
        __syncthreads();
    }
    {
        float4 ba = ((const float4*)b1)[tc * 2];
        float4 bb = ((const float4*)b1)[tc * 2 + 1];
        float bj[8] = {ba.x, ba.y, ba.z, ba.w, bb.x, bb.y, bb.z, bb.w};
#pragma unroll
        for (int i = 0; i < 4; i++)
#pragma unroll
            for (int j = 0; j < 8; j++) acc[i][j] += bj[j];
    }
    // combine pairs -> Fe (rows 0..31 of H_S), side-loss
    float lsum = 0.f;
#pragma unroll
    for (int pi = 0; pi < 2; pi++) {
        int p = tr * 2 + pi;
        float fe[8];
#pragma unroll
        for (int j = 0; j < 8; j++) {
            float m1 = acc[2 * pi][j], m2 = acc[2 * pi + 1][j];
            float df = m1 - m2; lsum += df * df;
            fe[j] = 0.5f * (m1 + m2);
        }
        *(float4*)&H_S[p * 132 + tc * 8]     = make_float4(fe[0], fe[1], fe[2], fe[3]);
        *(float4*)&H_S[p * 132 + tc * 8 + 4] = make_float4(fe[4], fe[5], fe[6], fe[7]);
    }
    if (tid < 32) {
        H_S[tid * 132 + 128] = act[pbase + tid];   // actions first
        H_S[tid * 132 + 129] = ang[pbase + tid];   // then angles
    }
    block_reduce_to(lossp, lsum, RED, tid);
    __syncthreads();

    // out[32,128] = [fe|act|ang] @ Wl[130,128] + bl
    float acc3[4][4];
#pragma unroll
    for (int i = 0; i < 4; i++)
#pragma unroll
        for (int j = 0; j < 4; j++) acc3[i][j] = 0.f;
    const int tr3 = tid >> 5, tc3 = tid & 31;
    for (int kc = 0; kc < 130; kc += 16) {
        int klen = (130 - kc) < 16 ? (130 - kc) : 16;
#pragma unroll
        for (int t = 0; t < 2; t++) {
            int idx = tid + t * 256;
            int kk = idx >> 5, n4 = idx & 31;
            if (kk < klen)
                *(float4*)&W_S[kk * 128 + n4 * 4] = ((const float4*)(Wl + (kc + kk) * 128))[n4];
        }
        __syncthreads();
        if (klen == 16) {
#pragma unroll
            for (int kk = 0; kk < 16; kk++) {
                float f0 = H_S[(tr3 * 4 + 0) * 132 + kc + kk];
                float f1 = H_S[(tr3 * 4 + 1) * 132 + kc + kk];
                float f2 = H_S[(tr3 * 4 + 2) * 132 + kc + kk];
                float f3 = H_S[(tr3 * 4 + 3) * 132 + kc + kk];
                float4 w = *(const float4*)&W_S[kk * 128 + tc3 * 4];
                acc3[0][0] += f0 * w.x; acc3[0][1] += f0 * w.y; acc3[0][2] += f0 * w.z; acc3[0][3] += f0 * w.w;
                acc3[1][0] += f1 * w.x; acc3[1][1] += f1 * w.y; acc3[1][2] += f1 * w.z; acc3[1][3] += f1 * w.w;
                acc3[2][0] += f2 * w.x; acc3[2][1] += f2 * w.y; acc3[2][2] += f2 * w.z; acc3[2][3] += f2 * w.w;
                acc3[3][0] += f3 * w.x; acc3[3][1] += f3 * w.y; acc3[3][2] += f3 * w.z; acc3[3][3] += f3 * w.w;
            }
        } else {
#pragma unroll
            for (int kk = 0; kk < 2; kk++) {
                float f0 = H_S[(tr3 * 4 + 0) * 132 + kc + kk];
                float f1 = H_S[(tr3 * 4 + 1) * 132 + kc + kk];
                float f2 = H_S[(tr3 * 4 + 2) * 132 + kc + kk];
                float f3 = H_S[(tr3 * 4 + 3) * 132 + kc + kk];
                float4 w = *(const float4*)&W_S[kk * 128 + tc3 * 4];
                acc3[0][0] += f0 * w.x; acc3[0][1] += f0 * w.y; acc3[0][2] += f0 * w.z; acc3[0][3] += f0 * w.w;
                acc3[1][0] += f1 * w.x; acc3[1][1] += f1 * w.y; acc3[1][2] += f1 * w.z; acc3[1][3] += f1 * w.w;
                acc3[2][0] += f2 * w.x; acc3[2][1] += f2 * w.y; acc3[2][2] += f2 * w.z; acc3[2][3] += f2 * w.w;
                acc3[3][0] += f3 * w.x; acc3[3][1] += f3 * w.y; acc3[3][2] += f3 * w.z; acc3[3][3] += f3 * w.w;
            }
        }
        __syncthreads();
    }
    float4 blv = ((const float4*)bl)[tc3];
#pragma unroll
    for (int i = 0; i < 4; i++) {
        int p = tr3 * 4 + i;
        *(float4*)&fe1[(size_t)(pbase + p) * 128 + tc3 * 4] =
            make_float4(acc3[i][0] + blv.x, acc3[i][1] + blv.y, acc3[i][2] + blv.z, acc3[i][3] + blv.w);
    }
}

// ------------------------------------------------------------------
__global__ void __launch_bounds__(256) edge_conv2_kernel(
    const float* __restrict__ P, const int* __restrict__ ei,
    const float* __restrict__ fe1,
    const float* __restrict__ b0,
    const float* __restrict__ W1, const float* __restrict__ b1,
    const float* __restrict__ Wl, const float* __restrict__ bl,
    float* __restrict__ out, double* __restrict__ lossp)
{
    __shared__ float sm[SMEM_FLOATS];
    float* W_S = sm;
    float* H_S = sm + 2048;
    int* SP = (int*)(sm + 10496);
    int* DP = (int*)(sm + 10528);
    float* RED = sm + 10560;
    // small regions inside W_S (used after H build):
    float* W1S = W_S;          // 384 floats (128x3)
    float* M_S = W_S + 384;    // 192 floats (64x3)
    float* FE2 = W_S + 576;    // 96 floats  (32x3)
    float* WL2 = W_S + 672;    // 393 floats (131x3)
    const int tid = threadIdx.x;
    const int pbase = blockIdx.x * 32;
    if (tid < 32) {
        SP[tid] = ei[pbase + tid];
        DP[tid] = ei[NP + pbase + tid];
        ((float4*)W_S)[tid] = ((const float4*)b0)[tid];
    }
    __syncthreads();
    build_H(P, W_S, H_S, SP, DP, tid);
    __syncthreads();

    // stage W1 (128x3)
    if (tid < 96) ((float4*)W1S)[tid] = ((const float4*)W1)[tid];
    __syncthreads();
    // M[64,3] = H @ W1 + b1
    if (tid < 192) {
        int r = tid & 63, c = tid >> 6;
        float s = b1[c];
#pragma unroll 4
        for (int k = 0; k < 128; k++) s += H_S[r * 132 + k] * W1S[k * 3 + c];
        M_S[r * 3 + c] = s;
    }
    __syncthreads();

    float lsum = 0.f;
    if (tid < 96) {
        int p = tid & 31, c = tid >> 5;
        float m1 = M_S[(2 * p) * 3 + c], m2 = M_S[(2 * p + 1) * 3 + c];
        float df = m1 - m2; lsum = df * df;
        FE2[p * 3 + c] = 0.5f * (m1 + m2);
    }
    // stage Wl (131x3)
    for (int i = tid; i < 393; i += 256) WL2[i] = Wl[i];
    // load fe1 rows into H_S (stride 132)
#pragma unroll
    for (int t = 0; t < 4; t++) {
        int idx = tid + t * 256;
        int pr = idx >> 5, c4 = idx & 31;
        *(float4*)&H_S[pr * 132 + c4 * 4] =
            ((const float4*)&fe1[(size_t)(pbase + pr) * 128])[c4];
    }
    block_reduce_to(lossp, lsum, RED, tid);
    __syncthreads();

    // out[32,3] = [fe2(3) | fe1(128)] @ Wl[131,3] + bl
    if (tid < 96) {
        int p = tid & 31, c = tid >> 5;
        float s = bl[c];
#pragma unroll
        for (int k = 0; k < 3; k++) s += FE2[p * 3 + k] * WL2[k * 3 + c];
#pragma unroll 4
        for (int k = 0; k < 128; k++) s += H_S[p * 132 + k] * WL2[(3 + k) * 3 + c];
        out[(size_t)(pbase + p) * 3 + c] = s;
    }
}

// ------------------------------------------------------------------
__global__ void finalize_kernel(float* __restrict__ out, int idx)
{
    double l = 0.5 * (g_loss[0] / (800000.0 * 128.0) + g_loss[1] / (800000.0 * 3.0));
    out[idx] = (float)l;
}

// ------------------------------------------------------------------
extern "C" void kernel_launch(void* const* d_in, const int* in_sizes, int n_in,
                              void* d_out, int out_size)
{
    (void)in_sizes; (void)n_in;
    const float* xnf  = (const float*)d_in[0];
    const int*   ei   = (const int*)d_in[1];
    const float* ang  = (const float*)d_in[2];
    const float* act  = (const float*)d_in[3];
    const float* nc1W0 = (const float*)d_in[5];
    const float* nc1b0 = (const float*)d_in[6];
    const float* nc1W1 = (const float*)d_in[7];
    const float* nc1b1 = (const float*)d_in[8];
    const float* ec1W0 = (const float*)d_in[9];
    const float* ec1b0 = (const float*)d_in[10];
    const float* ec1W1 = (const float*)d_in[11];
    const float* ec1b1 = (const float*)d_in[12];
    const float* ec1Wl = (const float*)d_in[13];
    const float* ec1bl = (const float*)d_in[14];
    const float* nc2W0 = (const float*)d_in[15];
    const float* nc2b0 = (const float*)d_in[16];
    const float* nc2W1 = (const float*)d_in[17];
    const float* nc2b1 = (const float*)d_in[18];
    const float* ec2W0 = (const float*)d_in[19];
    const float* ec2b0 = (const float*)d_in[20];
    const float* ec2W1 = (const float*)d_in[21];
    const float* ec2b1 = (const float*)d_in[22];
    const float* ec2Wl = (const float*)d_in[23];
    const float* ec2bl = (const float*)d_in[24];
    float* out = (float*)d_out;

    float *agg, *x1, *x2, *fe1, *PA, *PB;
    int* cnt;
    double* loss;
    cudaGetSymbolAddress((void**)&agg,  g_agg);
    cudaGetSymbolAddress((void**)&x1,   g_x1);
    cudaGetSymbolAddress((void**)&x2,   g_x2);
    cudaGetSymbolAddress((void**)&fe1,  g_fe1);
    cudaGetSymbolAddress((void**)&PA,   g_PA);
    cudaGetSymbolAddress((void**)&PB,   g_PB);
    cudaGetSymbolAddress((void**)&cnt,  g_cnt);
    cudaGetSymbolAddress((void**)&loss, g_loss);

    cudaMemsetAsync(agg, 0, (size_t)NN * 64 * sizeof(float));
    cudaMemsetAsync(cnt, 0, (size_t)NN * sizeof(int));
    cudaMemsetAsync(loss, 0, 2 * sizeof(double));

    const int NPROJ = (NN + 63) / 64;

    count_kernel<<<(NP + 255) / 256, 256>>>(ei, cnt);

    node_proj_kernel<<<NPROJ, 256>>>(xnf, nc1W0, PA);
    node_conv_kernel<<<NP / 32, 256>>>(PA, ei, nc1b0, nc1W1, nc1b1, agg);
    divide_kernel<<<(NN * 64 + 255) / 256, 256>>>(agg, cnt, x1);
    cudaMemsetAsync(agg, 0, (size_t)NN * 64 * sizeof(float));

    node_proj_kernel<<<NPROJ, 256>>>(x1, ec1W0, PB);
    edge_conv1_kernel<<<NP / 32, 256>>>(PB, ei, act, ang,
                                        ec1b0, ec1W1, ec1b1, ec1Wl, ec1bl,
                                        fe1, loss);

    node_proj_kernel<<<NPROJ, 256>>>(x1, nc2W0, PA);
    node_conv_kernel<<<NP / 32, 256>>>(PA, ei, nc2b0, nc2W1, nc2b1, agg);
    divide_kernel<<<(NN * 64 + 255) / 256, 256>>>(agg, cnt, x2);

    node_proj_kernel<<<NPROJ, 256>>>(x2, ec2W0, PB);
    edge_conv2_kernel<<<NP / 32, 256>>>(PB, ei, fe1,
                                        ec2b0, ec2W1, ec2b1, ec2Wl, ec2bl,
                                        out, loss + 1);
    finalize_kernel<<<1, 1>>>(out, out_size - 1);
}

// round 3
// speedup vs baseline: 2.6834x; 1.2395x over previous
#include <cuda_runtime.h>

#define NN 50000
#define NP 800000   // undirected pairs
#define NE 1600000  // directed edges

// ---------------- scratch (static device globals; no allocations) ----------------
__device__ float  g_x1[NN * 64];
__device__ float  g_x2[NN * 64];
__device__ float  g_hagg[NN * 128];
__device__ int    g_cnt[NN];
__device__ float  g_PA[NN * 256];
__device__ float  g_PB[NN * 256];
__device__ float  g_fe1[102400000];   // 800000 x 128
__device__ double g_loss[2];

// ================= shared helpers =================
__device__ __forceinline__ float lrelu(float z) { return z > 0.f ? z : 0.01f * z; }

// ---------------- edge_conv2 shared memory layout (floats) ----------------
// W_S : 2048 ; H_S : 64x132 ; SP/DP : 32 ints each ; RED : 32
#define SMEM2_FLOATS 10592

__device__ __forceinline__ void block_reduce_to256(double* target, float v, float* RED, int tid)
{
#pragma unroll
    for (int o = 16; o > 0; o >>= 1) v += __shfl_down_sync(0xffffffffu, v, o);
    if ((tid & 31) == 0) RED[tid >> 5] = v;
    __syncthreads();
    if (tid == 0) {
        float t = 0.f;
#pragma unroll
        for (int w = 0; w < 8; w++) t += RED[w];
        atomicAdd(target, (double)t);
    }
}

// H[64][132] = lrelu(Pt[a] + Pb[b] + b0) for 32 pairs (2 variants each)
__device__ __forceinline__ void build_H32(
    const float* __restrict__ P, const float* b0s, float* H_S,
    const int* SP, const int* DP, int tid)
{
#pragma unroll
    for (int it = 0; it < 8; it++) {
        int idx = tid + it * 256;
        int r = idx >> 5, c4 = idx & 31;
        int pp = r >> 1, v = r & 1;
        int na = v ? DP[pp] : SP[pp];
        int nb = v ? SP[pp] : DP[pp];
        float4 a = __ldg((const float4*)(P + (size_t)na * 256) + c4);
        float4 b = __ldg((const float4*)(P + (size_t)nb * 256) + 32 + c4);
        float4 h;
        h.x = lrelu(a.x + b.x + b0s[c4 * 4]);
        h.y = lrelu(a.y + b.y + b0s[c4 * 4 + 1]);
        h.z = lrelu(a.z + b.z + b0s[c4 * 4 + 2]);
        h.w = lrelu(a.w + b.w + b0s[c4 * 4 + 3]);
        *(float4*)&H_S[r * 132 + c4 * 4] = h;
    }
}

// ------------------------------------------------------------------
// P[n][0..127] = x[n] @ W0[0:64,:]  ; P[n][128..255] = x[n] @ W0[64:128,:]
__global__ void __launch_bounds__(256) node_proj_kernel(
    const float* __restrict__ x, const float* __restrict__ W0, float* __restrict__ P)
{
    __shared__ float XT[64 * 68];
    __shared__ float WC[16 * 256];
    const int tid = threadIdx.x;
    const int nbase = blockIdx.x * 64;
#pragma unroll
    for (int i = 0; i < 4; i++) {
        int lin = tid * 4 + i;
        int r = lin >> 4, q = lin & 15;
        int node = nbase + r; if (node >= NN) node = NN - 1;
        float4 v = __ldg((const float4*)x + (size_t)node * 16 + q);
        XT[(q * 4 + 0) * 68 + r] = v.x;
        XT[(q * 4 + 1) * 68 + r] = v.y;
        XT[(q * 4 + 2) * 68 + r] = v.z;
        XT[(q * 4 + 3) * 68 + r] = v.w;
    }
    float acc[8][8];
#pragma unroll
    for (int i = 0; i < 8; i++)
#pragma unroll
        for (int j = 0; j < 8; j++) acc[i][j] = 0.f;
    const int tr = tid >> 5, tc = tid & 31;
    for (int kc = 0; kc < 64; kc += 16) {
        __syncthreads();
#pragma unroll
        for (int i = 0; i < 4; i++) {
            int lin = tid + i * 256;
            int kk = lin >> 6, j4 = lin & 63;
            int j = j4 * 4;
            const float* src = (j < 128) ? (W0 + (kc + kk) * 128 + j)
                                         : (W0 + (64 + kc + kk) * 128 + (j - 128));
            *(float4*)&WC[kk * 256 + j] = *(const float4*)src;
        }
        __syncthreads();
#pragma unroll
        for (int kk = 0; kk < 16; kk++) {
            float4 a0 = *(const float4*)&XT[(kc + kk) * 68 + tr * 8];
            float4 a1 = *(const float4*)&XT[(kc + kk) * 68 + tr * 8 + 4];
            float4 w0 = *(const float4*)&WC[kk * 256 + tc * 8];
            float4 w1 = *(const float4*)&WC[kk * 256 + tc * 8 + 4];
            float a[8] = {a0.x, a0.y, a0.z, a0.w, a1.x, a1.y, a1.z, a1.w};
            float w[8] = {w0.x, w0.y, w0.z, w0.w, w1.x, w1.y, w1.z, w1.w};
#pragma unroll
            for (int i = 0; i < 8; i++)
#pragma unroll
                for (int j = 0; j < 8; j++) acc[i][j] += a[i] * w[j];
        }
    }
#pragma unroll
    for (int i = 0; i < 8; i++) {
        int node = nbase + tr * 8 + i;
        if (node < NN) {
            *(float4*)&P[(size_t)node * 256 + tc * 8] =
                make_float4(acc[i][0], acc[i][1], acc[i][2], acc[i][3]);
            *(float4*)&P[(size_t)node * 256 + tc * 8 + 4] =
                make_float4(acc[i][4], acc[i][5], acc[i][6], acc[i][7]);
        }
    }
}

// ------------------------------------------------------------------
__global__ void count_kernel(const int* __restrict__ ei, int* __restrict__ cnt)
{
    int j = blockIdx.x * blockDim.x + threadIdx.x;
    if (j < NP) {
        atomicAdd(&cnt[ei[j]], 1);
        atomicAdd(&cnt[ei[NP + j]], 1);
    }
}

// ------------------------------------------------------------------
// Per directed edge e: h = lrelu(Pt[src] + Pb[dst] + b0); Hagg[dst] += h
__global__ void __launch_bounds__(256) scatter_kernel(
    const float* __restrict__ P, const int* __restrict__ ei,
    const float* __restrict__ b0, float* __restrict__ Hagg)
{
    const int tid = threadIdx.x;
    const int lane = tid & 31;
    const int e = (blockIdx.x * 256 + tid) >> 5;
    if (e >= NE) return;
    const int src = ei[e];
    const int dst = ei[NE + e];
    float4 a = __ldg((const float4*)(P + (size_t)src * 256) + lane);
    float4 b = __ldg((const float4*)(P + (size_t)dst * 256) + 32 + lane);
    float4 b0v = __ldg((const float4*)b0 + lane);
    float h0 = lrelu(a.x + b.x + b0v.x);
    float h1 = lrelu(a.y + b.y + b0v.y);
    float h2 = lrelu(a.z + b.z + b0v.z);
    float h3 = lrelu(a.w + b.w + b0v.w);
    float* dp = Hagg + (size_t)dst * 128 + lane * 4;
    atomicAdd(dp + 0, h0);
    atomicAdd(dp + 1, h1);
    atomicAdd(dp + 2, h2);
    atomicAdd(dp + 3, h3);
}

// ------------------------------------------------------------------
// x[n] = (Hagg[n] @ W1)/max(cnt,1) + b1*(cnt>0)
__global__ void __launch_bounds__(256) node_gemm_kernel(
    const float* __restrict__ Hagg, const int* __restrict__ cnt,
    const float* __restrict__ W1, const float* __restrict__ b1,
    float* __restrict__ x)
{
    __shared__ float HT[128 * 68];   // 8704
    __shared__ float W1S[32 * 64];   // 2048
    const int tid = threadIdx.x;
    const int nbase = blockIdx.x * 64;
#pragma unroll
    for (int it = 0; it < 8; it++) {
        int lin = tid + it * 256;
        int n = lin >> 5, q = lin & 31;
        int node = nbase + n; if (node >= NN) node = NN - 1;
        float4 v = *((const float4*)(Hagg + (size_t)node * 128) + q);
        HT[(q * 4 + 0) * 68 + n] = v.x;
        HT[(q * 4 + 1) * 68 + n] = v.y;
        HT[(q * 4 + 2) * 68 + n] = v.z;
        HT[(q * 4 + 3) * 68 + n] = v.w;
    }
    float acc[4][4];
#pragma unroll
    for (int i = 0; i < 4; i++)
#pragma unroll
        for (int j = 0; j < 4; j++) acc[i][j] = 0.f;
    const int tr = tid >> 4, tc = tid & 15;
    for (int kc = 0; kc < 128; kc += 32) {
        __syncthreads();
#pragma unroll
        for (int t = 0; t < 2; t++) {
            int lin = tid + t * 256;
            int kk = lin >> 4, c4 = lin & 15;
            *(float4*)&W1S[kk * 64 + c4 * 4] = *(const float4*)(W1 + (kc + kk) * 64 + c4 * 4);
        }
        __syncthreads();
#pragma unroll
        for (int kk = 0; kk < 32; kk++) {
            float a0 = HT[(kc + kk) * 68 + tr * 4 + 0];
            float a1 = HT[(kc + kk) * 68 + tr * 4 + 1];
            float a2 = HT[(kc + kk) * 68 + tr * 4 + 2];
            float a3 = HT[(kc + kk) * 68 + tr * 4 + 3];
            float4 w = *(const float4*)&W1S[kk * 64 + tc * 4];
            acc[0][0] += a0 * w.x; acc[0][1] += a0 * w.y; acc[0][2] += a0 * w.z; acc[0][3] += a0 * w.w;
            acc[1][0] += a1 * w.x; acc[1][1] += a1 * w.y; acc[1][2] += a1 * w.z; acc[1][3] += a1 * w.w;
            acc[2][0] += a2 * w.x; acc[2][1] += a2 * w.y; acc[2][2] += a2 * w.z; acc[2][3] += a2 * w.w;
            acc[3][0] += a3 * w.x; acc[3][1] += a3 * w.y; acc[3][2] += a3 * w.z; acc[3][3] += a3 * w.w;
        }
    }
#pragma unroll
    for (int i = 0; i < 4; i++) {
        int node = nbase + tr * 4 + i;
        if (node < NN) {
            int c = cnt[node];
            float inv = 1.f / fmaxf((float)c, 1.f);
            float bf = c > 0 ? 1.f : 0.f;
            float4 bv = *((const float4*)b1 + tc);
            *(float4*)&x[(size_t)node * 64 + tc * 4] = make_float4(
                acc[i][0] * inv + bv.x * bf, acc[i][1] * inv + bv.y * bf,
                acc[i][2] * inv + bv.z * bf, acc[i][3] * inv + bv.w * bf);
        }
    }
}

// ------------------------------------------------------------------
// edge_conv1: persistent weights, 512 threads, 64 pairs per tile, grid-stride
// smem floats: W1S 16384 | WLS 16640 | H_S 16896 | SP 64 | DP 64 | B0S 128 |
//              B1S 128 | BLS 128 | RED 16
#define EC1_W1S   0
#define EC1_WLS   16384
#define EC1_HS    33024
#define EC1_SP    49920
#define EC1_DP    49984
#define EC1_B0S   50048
#define EC1_B1S   50176
#define EC1_BLS   50304
#define EC1_RED   50432
#define EC1_FLOATS 50448
#define EC1_NTILE 12500

__global__ void __launch_bounds__(512) edge_conv1_kernel(
    const float* __restrict__ P, const int* __restrict__ ei,
    const float* __restrict__ act, const float* __restrict__ ang,
    const float* __restrict__ b0,
    const float* __restrict__ W1, const float* __restrict__ b1,
    const float* __restrict__ Wl, const float* __restrict__ bl,
    float* __restrict__ fe1, double* __restrict__ lossp)
{
    extern __shared__ float sm[];
    float* W1S = sm + EC1_W1S;
    float* WLS = sm + EC1_WLS;
    float* H_S = sm + EC1_HS;
    int* SP = (int*)(sm + EC1_SP);
    int* DP = (int*)(sm + EC1_DP);
    float* B0S = sm + EC1_B0S;
    float* B1S = sm + EC1_B1S;
    float* BLS = sm + EC1_BLS;
    float* RED = sm + EC1_RED;
    const int tid = threadIdx.x;

    // load resident weights once
    for (int i = tid; i < 4096; i += 512)
        ((float4*)W1S)[i] = ((const float4*)W1)[i];
    for (int i = tid; i < 4160; i += 512)
        ((float4*)WLS)[i] = ((const float4*)Wl)[i];
    if (tid < 32) {
        ((float4*)B0S)[tid] = ((const float4*)b0)[tid];
        ((float4*)B1S)[tid] = ((const float4*)b1)[tid];
        ((float4*)BLS)[tid] = ((const float4*)bl)[tid];
    }
    __syncthreads();

    const int tr = tid >> 4, tc = tid & 15;       // phase2: 32x16
    const int tr3 = tid >> 5, tc3 = tid & 31;     // phase3: 16x32
    float lsum = 0.f;

    for (int tile = blockIdx.x; tile < EC1_NTILE; tile += gridDim.x) {
        const int pbase = tile * 64;
        if (tid < 64) {
            SP[tid] = ei[pbase + tid];
            DP[tid] = ei[NP + pbase + tid];
        }
        __syncthreads();
        // build H: 128 rows (pair p: row 2p = (s,d), row 2p+1 = (d,s))
#pragma unroll
        for (int it = 0; it < 8; it++) {
            int idx = tid + it * 512;
            int r = idx >> 5, c4 = idx & 31;
            int pp = r >> 1, v = r & 1;
            int na = v ? DP[pp] : SP[pp];
            int nb = v ? SP[pp] : DP[pp];
            float4 a = __ldg((const float4*)(P + (size_t)na * 256) + c4);
            float4 b = __ldg((const float4*)(P + (size_t)nb * 256) + 32 + c4);
            float4 h;
            h.x = lrelu(a.x + b.x + B0S[c4 * 4]);
            h.y = lrelu(a.y + b.y + B0S[c4 * 4 + 1]);
            h.z = lrelu(a.z + b.z + B0S[c4 * 4 + 2]);
            h.w = lrelu(a.w + b.w + B0S[c4 * 4 + 3]);
            *(float4*)&H_S[r * 132 + c4 * 4] = h;
        }
        __syncthreads();

        // phase2: M[128,128] = H @ W1 (+b1 in epilogue)
        float acc[4][8];
#pragma unroll
        for (int i = 0; i < 4; i++)
#pragma unroll
            for (int j = 0; j < 8; j++) acc[i][j] = 0.f;
#pragma unroll 4
        for (int kk = 0; kk < 128; kk++) {
            float h0 = H_S[(tr * 4 + 0) * 132 + kk];
            float h1 = H_S[(tr * 4 + 1) * 132 + kk];
            float h2 = H_S[(tr * 4 + 2) * 132 + kk];
            float h3 = H_S[(tr * 4 + 3) * 132 + kk];
            float4 w0 = *(const float4*)&W1S[kk * 128 + tc * 8];
            float4 w1 = *(const float4*)&W1S[kk * 128 + tc * 8 + 4];
            float w[8] = {w0.x, w0.y, w0.z, w0.w, w1.x, w1.y, w1.z, w1.w};
            float h[4] = {h0, h1, h2, h3};
#pragma unroll
            for (int i = 0; i < 4; i++)
#pragma unroll
                for (int j = 0; j < 8; j++) acc[i][j] += h[i] * w[j];
        }
        {
            float bj[8];
#pragma unroll
            for (int j = 0; j < 8; j++) bj[j] = B1S[tc * 8 + j];
#pragma unroll
            for (int i = 0; i < 4; i++)
#pragma unroll
                for (int j = 0; j < 8; j++) acc[i][j] += bj[j];
        }
        __syncthreads();   // all phase2 H reads complete before fe overwrite

        // combine pairs -> fe rows [0..63] of H_S, accumulate loss
#pragma unroll
        for (int pi = 0; pi < 2; pi++) {
            int p = tr * 2 + pi;
            float fe[8];
#pragma unroll
            for (int j = 0; j < 8; j++) {
                float m1 = acc[2 * pi][j], m2 = acc[2 * pi + 1][j];
                float df = m1 - m2; lsum += df * df;
                fe[j] = 0.5f * (m1 + m2);
            }
            *(float4*)&H_S[p * 132 + tc * 8]     = make_float4(fe[0], fe[1], fe[2], fe[3]);
            *(float4*)&H_S[p * 132 + tc * 8 + 4] = make_float4(fe[4], fe[5], fe[6], fe[7]);
        }
        if (tid < 64) {
            H_S[tid * 132 + 128] = act[pbase + tid];
            H_S[tid * 132 + 129] = ang[pbase + tid];
        }
        __syncthreads();

        // phase3: out[64,128] = [fe|act|ang] @ Wl[130,128] + bl
        float acc3[4][4];
#pragma unroll
        for (int i = 0; i < 4; i++)
#pragma unroll
            for (int j = 0; j < 4; j++) acc3[i][j] = 0.f;
#pragma unroll 2
        for (int k = 0; k < 130; k++) {
            float f0 = H_S[(tr3 * 4 + 0) * 132 + k];
            float f1 = H_S[(tr3 * 4 + 1) * 132 + k];
            float f2 = H_S[(tr3 * 4 + 2) * 132 + k];
            float f3 = H_S[(tr3 * 4 + 3) * 132 + k];
            float4 w = *(const float4*)&WLS[k * 128 + tc3 * 4];
            acc3[0][0] += f0 * w.x; acc3[0][1] += f0 * w.y; acc3[0][2] += f0 * w.z; acc3[0][3] += f0 * w.w;
            acc3[1][0] += f1 * w.x; acc3[1][1] += f1 * w.y; acc3[1][2] += f1 * w.z; acc3[1][3] += f1 * w.w;
            acc3[2][0] += f2 * w.x; acc3[2][1] += f2 * w.y; acc3[2][2] += f2 * w.z; acc3[2][3] += f2 * w.w;
            acc3[3][0] += f3 * w.x; acc3[3][1] += f3 * w.y; acc3[3][2] += f3 * w.z; acc3[3][3] += f3 * w.w;
        }
        {
            float4 blv = *(const float4*)&BLS[tc3 * 4];
#pragma unroll
            for (int i = 0; i < 4; i++) {
                int p = tr3 * 4 + i;
                *(float4*)&fe1[(size_t)(pbase + p) * 128 + tc3 * 4] =
                    make_float4(acc3[i][0] + blv.x, acc3[i][1] + blv.y,
                                acc3[i][2] + blv.z, acc3[i][3] + blv.w);
            }
        }
        __syncthreads();   // phase3 reads done before next tile's H build
    }

    // loss reduce (512 threads -> 16 warps)
#pragma unroll
    for (int o = 16; o > 0; o >>= 1) lsum += __shfl_down_sync(0xffffffffu, lsum, o);
    if ((tid & 31) == 0) RED[tid >> 5] = lsum;
    __syncthreads();
    if (tid == 0) {
        float t = 0.f;
#pragma unroll
        for (int w = 0; w < 16; w++) t += RED[w];
        atomicAdd(lossp, (double)t);
    }
}

// ------------------------------------------------------------------
__global__ void __launch_bounds__(256) edge_conv2_kernel(
    const float* __restrict__ P, const int* __restrict__ ei,
    const float* __restrict__ fe1,
    const float* __restrict__ b0,
    const float* __restrict__ W1, const float* __restrict__ b1,
    const float* __restrict__ Wl, const float* __restrict__ bl,
    float* __restrict__ out, double* __restrict__ lossp)
{
    __shared__ float sm[SMEM2_FLOATS];
    float* W_S = sm;
    float* H_S = sm + 2048;
    int* SP = (int*)(sm + 10496);
    int* DP = (int*)(sm + 10528);
    float* RED = sm + 10560;
    float* W1S = W_S;          // 384 floats (128x3)
    float* M_S = W_S + 384;    // 192 floats (64x3)
    float* FE2 = W_S + 576;    // 96 floats  (32x3)
    float* WL2 = W_S + 672;    // 393 floats (131x3)
    const int tid = threadIdx.x;
    const int pbase = blockIdx.x * 32;
    if (tid < 32) {
        SP[tid] = ei[pbase + tid];
        DP[tid] = ei[NP + pbase + tid];
        ((float4*)W_S)[tid] = ((const float4*)b0)[tid];
    }
    __syncthreads();
    build_H32(P, W_S, H_S, SP, DP, tid);
    __syncthreads();

    if (tid < 96) ((float4*)W1S)[tid] = ((const float4*)W1)[tid];
    __syncthreads();
    if (tid < 192) {
        int r = tid & 63, c = tid >> 6;
        float s = b1[c];
#pragma unroll 4
        for (int k = 0; k < 128; k++) s += H_S[r * 132 + k] * W1S[k * 3 + c];
        M_S[r * 3 + c] = s;
    }
    __syncthreads();

    float lsum = 0.f;
    if (tid < 96) {
        int p = tid & 31, c = tid >> 5;
        float m1 = M_S[(2 * p) * 3 + c], m2 = M_S[(2 * p + 1) * 3 + c];
        float df = m1 - m2; lsum = df * df;
        FE2[p * 3 + c] = 0.5f * (m1 + m2);
    }
    for (int i = tid; i < 393; i += 256) WL2[i] = Wl[i];
#pragma unroll
    for (int t = 0; t < 4; t++) {
        int idx = tid + t * 256;
        int pr = idx >> 5, c4 = idx & 31;
        *(float4*)&H_S[pr * 132 + c4 * 4] =
            ((const float4*)&fe1[(size_t)(pbase + pr) * 128])[c4];
    }
    block_reduce_to256(lossp, lsum, RED, tid);
    __syncthreads();

    if (tid < 96) {
        int p = tid & 31, c = tid >> 5;
        float s = bl[c];
#pragma unroll
        for (int k = 0; k < 3; k++) s += FE2[p * 3 + k] * WL2[k * 3 + c];
#pragma unroll 4
        for (int k = 0; k < 128; k++) s += H_S[p * 132 + k] * WL2[(3 + k) * 3 + c];
        out[(size_t)(pbase + p) * 3 + c] = s;
    }
}

// ------------------------------------------------------------------
__global__ void finalize_kernel(float* __restrict__ out, int idx)
{
    double l = 0.5 * (g_loss[0] / (800000.0 * 128.0) + g_loss[1] / (800000.0 * 3.0));
    out[idx] = (float)l;
}

// ------------------------------------------------------------------
extern "C" void kernel_launch(void* const* d_in, const int* in_sizes, int n_in,
                              void* d_out, int out_size)
{
    (void)in_sizes; (void)n_in;
    const float* xnf  = (const float*)d_in[0];
    const int*   ei   = (const int*)d_in[1];
    const float* ang  = (const float*)d_in[2];
    const float* act  = (const float*)d_in[3];
    const float* nc1W0 = (const float*)d_in[5];
    const float* nc1b0 = (const float*)d_in[6];
    const float* nc1W1 = (const float*)d_in[7];
    const float* nc1b1 = (const float*)d_in[8];
    const float* ec1W0 = (const float*)d_in[9];
    const float* ec1b0 = (const float*)d_in[10];
    const float* ec1W1 = (const float*)d_in[11];
    const float* ec1b1 = (const float*)d_in[12];
    const float* ec1Wl = (const float*)d_in[13];
    const float* ec1bl = (const float*)d_in[14];
    const float* nc2W0 = (const float*)d_in[15];
    const float* nc2b0 = (const float*)d_in[16];
    const float* nc2W1 = (const float*)d_in[17];
    const float* nc2b1 = (const float*)d_in[18];
    const float* ec2W0 = (const float*)d_in[19];
    const float* ec2b0 = (const float*)d_in[20];
    const float* ec2W1 = (const float*)d_in[21];
    const float* ec2b1 = (const float*)d_in[22];
    const float* ec2Wl = (const float*)d_in[23];
    const float* ec2bl = (const float*)d_in[24];
    float* out = (float*)d_out;

    float *hagg, *x1, *x2, *fe1, *PA, *PB;
    int* cnt;
    double* loss;
    cudaGetSymbolAddress((void**)&hagg, g_hagg);
    cudaGetSymbolAddress((void**)&x1,   g_x1);
    cudaGetSymbolAddress((void**)&x2,   g_x2);
    cudaGetSymbolAddress((void**)&fe1,  g_fe1);
    cudaGetSymbolAddress((void**)&PA,   g_PA);
    cudaGetSymbolAddress((void**)&PB,   g_PB);
    cudaGetSymbolAddress((void**)&cnt,  g_cnt);
    cudaGetSymbolAddress((void**)&loss, g_loss);

    static int attr_done = 0;
    if (!attr_done) {
        cudaFuncSetAttribute(edge_conv1_kernel,
                             cudaFuncAttributeMaxDynamicSharedMemorySize,
                             EC1_FLOATS * sizeof(float));
        attr_done = 1;
    }

    cudaMemsetAsync(hagg, 0, (size_t)NN * 128 * sizeof(float));
    cudaMemsetAsync(cnt, 0, (size_t)NN * sizeof(int));
    cudaMemsetAsync(loss, 0, 2 * sizeof(double));

    const int NPROJ = (NN + 63) / 64;
    const int NGEMM = (NN + 63) / 64;

    count_kernel<<<(NP + 255) / 256, 256>>>(ei, cnt);

    // ---- conv layer 1 (node) ----
    node_proj_kernel<<<NPROJ, 256>>>(xnf, nc1W0, PA);
    scatter_kernel<<<NE / 8, 256>>>(PA, ei, nc1b0, hagg);
    node_gemm_kernel<<<NGEMM, 256>>>(hagg, cnt, nc1W1, nc1b1, x1);

    // ---- edge conv 1 ----
    node_proj_kernel<<<NPROJ, 256>>>(x1, ec1W0, PB);
    edge_conv1_kernel<<<1184, 512, EC1_FLOATS * sizeof(float)>>>(
        PB, ei, act, ang, ec1b0, ec1W1, ec1b1, ec1Wl, ec1bl, fe1, loss);

    // ---- conv layer 2 (node) ----
    cudaMemsetAsync(hagg, 0, (size_t)NN * 128 * sizeof(float));
    node_proj_kernel<<<NPROJ, 256>>>(x1, nc2W0, PA);
    scatter_kernel<<<NE / 8, 256>>>(PA, ei, nc2b0, hagg);
    node_gemm_kernel<<<NGEMM, 256>>>(hagg, cnt, nc2W1, nc2b1, x2);

    // ---- edge conv 2 ----
    node_proj_kernel<<<NPROJ, 256>>>(x2, ec2W0, PA);
    edge_conv2_kernel<<<NP / 32, 256>>>(PA, ei, fe1,
                                        ec2b0, ec2W1, ec2b1, ec2Wl, ec2bl,
                                        out, loss + 1);
    finalize_kernel<<<1, 1>>>(out, out_size - 1);
}

// round 4
// speedup vs baseline: 3.0116x; 1.1223x over previous
#include <cuda_runtime.h>

#define NN 50000
#define NP 800000   // undirected pairs
#define NE 1600000  // directed edges

// ---------------- scratch (static device globals; no allocations) ----------------
__device__ float  g_x1[NN * 64];
__device__ float  g_x2[NN * 64];
__device__ float  g_hagg[NN * 128];
__device__ int    g_cnt[NN];
__device__ float  g_PA[NN * 256];
__device__ float  g_PB[NN * 256];
__device__ float  g_fe1[102400000];   // 800000 x 128
__device__ float  g_Wc[16384];        // W1 @ Wl[0:128]  (edge_conv1 fused)
__device__ float  g_c0[128];          // b1 @ Wl[0:128] + bl
__device__ float  g_Wc2[384];         // 0.5 * W1e2 @ Wl2[0:3]
__device__ float  g_c2[4];            // b1e2 @ Wl2[0:3] + bl2
__device__ double g_loss[2];

__device__ __forceinline__ float lrelu(float z) { return z > 0.f ? z : 0.01f * z; }

// ---------------- packed f32x2 helpers ----------------
__device__ __forceinline__ unsigned long long pack2(float x)
{
    unsigned long long r;
    asm("mov.b64 %0, {%1, %1};" : "=l"(r) : "f"(x));
    return r;
}
__device__ __forceinline__ unsigned long long ffma2(
    unsigned long long a, unsigned long long b, unsigned long long c)
{
    unsigned long long d;
    asm("fma.rn.f32x2 %0, %1, %2, %3;" : "=l"(d) : "l"(a), "l"(b), "l"(c));
    return d;
}
__device__ __forceinline__ void unpack2(unsigned long long v, float& lo, float& hi)
{
    asm("mov.b64 {%0, %1}, %2;" : "=f"(lo), "=f"(hi) : "l"(v));
}

// ------------------------------------------------------------------
// Weight fusion precompute kernels
__global__ void fuseA_kernel(const float* __restrict__ W1, const float* __restrict__ Wl,
                             float* __restrict__ Wc)
{
    int id = blockIdx.x * 256 + threadIdx.x;   // 16384
    int r = id >> 7, c = id & 127;
    float s = 0.f;
#pragma unroll 8
    for (int k = 0; k < 128; k++) s += W1[r * 128 + k] * Wl[k * 128 + c];
    Wc[id] = s;
}
__global__ void fuseA2_kernel(const float* __restrict__ Wl, const float* __restrict__ b1,
                              const float* __restrict__ bl, float* __restrict__ c0)
{
    int c = threadIdx.x;   // 128
    float s = bl[c];
#pragma unroll 8
    for (int k = 0; k < 128; k++) s += b1[k] * Wl[k * 128 + c];
    c0[c] = s;
}
__global__ void fuseB_kernel(const float* __restrict__ W1e, const float* __restrict__ Wl2,
                             const float* __restrict__ b1, const float* __restrict__ bl,
                             float* __restrict__ Wc2, float* __restrict__ c2)
{
    int id = threadIdx.x;   // 384
    if (id < 384) {
        int k = id / 3, c = id % 3;
        Wc2[id] = 0.5f * (W1e[k * 3 + 0] * Wl2[0 + c] +
                          W1e[k * 3 + 1] * Wl2[3 + c] +
                          W1e[k * 3 + 2] * Wl2[6 + c]);
    }
    if (id < 3)
        c2[id] = b1[0] * Wl2[0 + id] + b1[1] * Wl2[3 + id] + b1[2] * Wl2[6 + id] + bl[id];
}

// ------------------------------------------------------------------
// P[n][0..127] = x[n] @ W0[0:64,:]  ; P[n][128..255] = x[n] @ W0[64:128,:]
__global__ void __launch_bounds__(256) node_proj_kernel(
    const float* __restrict__ x, const float* __restrict__ W0, float* __restrict__ P)
{
    __shared__ float XT[64 * 68];
    __shared__ float WC[16 * 256];
    const int tid = threadIdx.x;
    const int nbase = blockIdx.x * 64;
#pragma unroll
    for (int i = 0; i < 4; i++) {
        int lin = tid * 4 + i;
        int r = lin >> 4, q = lin & 15;
        int node = nbase + r; if (node >= NN) node = NN - 1;
        float4 v = __ldg((const float4*)x + (size_t)node * 16 + q);
        XT[(q * 4 + 0) * 68 + r] = v.x;
        XT[(q * 4 + 1) * 68 + r] = v.y;
        XT[(q * 4 + 2) * 68 + r] = v.z;
        XT[(q * 4 + 3) * 68 + r] = v.w;
    }
    float acc[8][8];
#pragma unroll
    for (int i = 0; i < 8; i++)
#pragma unroll
        for (int j = 0; j < 8; j++) acc[i][j] = 0.f;
    const int tr = tid >> 5, tc = tid & 31;
    for (int kc = 0; kc < 64; kc += 16) {
        __syncthreads();
#pragma unroll
        for (int i = 0; i < 4; i++) {
            int lin = tid + i * 256;
            int kk = lin >> 6, j4 = lin & 63;
            int j = j4 * 4;
            const float* src = (j < 128) ? (W0 + (kc + kk) * 128 + j)
                                         : (W0 + (64 + kc + kk) * 128 + (j - 128));
            *(float4*)&WC[kk * 256 + j] = *(const float4*)src;
        }
        __syncthreads();
#pragma unroll
        for (int kk = 0; kk < 16; kk++) {
            float4 a0 = *(const float4*)&XT[(kc + kk) * 68 + tr * 8];
            float4 a1 = *(const float4*)&XT[(kc + kk) * 68 + tr * 8 + 4];
            float4 w0 = *(const float4*)&WC[kk * 256 + tc * 8];
            float4 w1 = *(const float4*)&WC[kk * 256 + tc * 8 + 4];
            float a[8] = {a0.x, a0.y, a0.z, a0.w, a1.x, a1.y, a1.z, a1.w};
            float w[8] = {w0.x, w0.y, w0.z, w0.w, w1.x, w1.y, w1.z, w1.w};
#pragma unroll
            for (int i = 0; i < 8; i++)
#pragma unroll
                for (int j = 0; j < 8; j++) acc[i][j] += a[i] * w[j];
        }
    }
#pragma unroll
    for (int i = 0; i < 8; i++) {
        int node = nbase + tr * 8 + i;
        if (node < NN) {
            *(float4*)&P[(size_t)node * 256 + tc * 8] =
                make_float4(acc[i][0], acc[i][1], acc[i][2], acc[i][3]);
            *(float4*)&P[(size_t)node * 256 + tc * 8 + 4] =
                make_float4(acc[i][4], acc[i][5], acc[i][6], acc[i][7]);
        }
    }
}

// ------------------------------------------------------------------
__global__ void count_kernel(const int* __restrict__ ei, int* __restrict__ cnt)
{
    int j = blockIdx.x * blockDim.x + threadIdx.x;
    if (j < NP) {
        atomicAdd(&cnt[ei[j]], 1);
        atomicAdd(&cnt[ei[NP + j]], 1);
    }
}

// ------------------------------------------------------------------
// Per directed edge e: h = lrelu(Pt[src] + Pb[dst] + b0); Hagg[dst] += h
__global__ void __launch_bounds__(256) scatter_kernel(
    const float* __restrict__ P, const int* __restrict__ ei,
    const float* __restrict__ b0, float* __restrict__ Hagg)
{
    const int tid = threadIdx.x;
    const int lane = tid & 31;
    const int e = (blockIdx.x * 256 + tid) >> 5;
    if (e >= NE) return;
    const int src = ei[e];
    const int dst = ei[NE + e];
    float4 a = __ldg((const float4*)(P + (size_t)src * 256) + lane);
    float4 b = __ldg((const float4*)(P + (size_t)dst * 256) + 32 + lane);
    float4 b0v = __ldg((const float4*)b0 + lane);
    float h0 = lrelu(a.x + b.x + b0v.x);
    float h1 = lrelu(a.y + b.y + b0v.y);
    float h2 = lrelu(a.z + b.z + b0v.z);
    float h3 = lrelu(a.w + b.w + b0v.w);
    float* dp = Hagg + (size_t)dst * 128 + lane * 4;
    atomicAdd(dp + 0, h0);
    atomicAdd(dp + 1, h1);
    atomicAdd(dp + 2, h2);
    atomicAdd(dp + 3, h3);
}

// ------------------------------------------------------------------
// x[n] = (Hagg[n] @ W1)/max(cnt,1) + b1*(cnt>0)
__global__ void __launch_bounds__(256) node_gemm_kernel(
    const float* __restrict__ Hagg, const int* __restrict__ cnt,
    const float* __restrict__ W1, const float* __restrict__ b1,
    float* __restrict__ x)
{
    __shared__ float HT[128 * 68];
    __shared__ float W1S[32 * 64];
    const int tid = threadIdx.x;
    const int nbase = blockIdx.x * 64;
#pragma unroll
    for (int it = 0; it < 8; it++) {
        int lin = tid + it * 256;
        int n = lin >> 5, q = lin & 31;
        int node = nbase + n; if (node >= NN) node = NN - 1;
        float4 v = *((const float4*)(Hagg + (size_t)node * 128) + q);
        HT[(q * 4 + 0) * 68 + n] = v.x;
        HT[(q * 4 + 1) * 68 + n] = v.y;
        HT[(q * 4 + 2) * 68 + n] = v.z;
        HT[(q * 4 + 3) * 68 + n] = v.w;
    }
    float acc[4][4];
#pragma unroll
    for (int i = 0; i < 4; i++)
#pragma unroll
        for (int j = 0; j < 4; j++) acc[i][j] = 0.f;
    const int tr = tid >> 4, tc = tid & 15;
    for (int kc = 0; kc < 128; kc += 32) {
        __syncthreads();
#pragma unroll
        for (int t = 0; t < 2; t++) {
            int lin = tid + t * 256;
            int kk = lin >> 4, c4 = lin & 15;
            *(float4*)&W1S[kk * 64 + c4 * 4] = *(const float4*)(W1 + (kc + kk) * 64 + c4 * 4);
        }
        __syncthreads();
#pragma unroll
        for (int kk = 0; kk < 32; kk++) {
            float a0 = HT[(kc + kk) * 68 + tr * 4 + 0];
            float a1 = HT[(kc + kk) * 68 + tr * 4 + 1];
            float a2 = HT[(kc + kk) * 68 + tr * 4 + 2];
            float a3 = HT[(kc + kk) * 68 + tr * 4 + 3];
            float4 w = *(const float4*)&W1S[kk * 64 + tc * 4];
            acc[0][0] += a0 * w.x; acc[0][1] += a0 * w.y; acc[0][2] += a0 * w.z; acc[0][3] += a0 * w.w;
            acc[1][0] += a1 * w.x; acc[1][1] += a1 * w.y; acc[1][2] += a1 * w.z; acc[1][3] += a1 * w.w;
            acc[2][0] += a2 * w.x; acc[2][1] += a2 * w.y; acc[2][2] += a2 * w.z; acc[2][3] += a2 * w.w;
            acc[3][0] += a3 * w.x; acc[3][1] += a3 * w.y; acc[3][2] += a3 * w.z; acc[3][3] += a3 * w.w;
        }
    }
#pragma unroll
    for (int i = 0; i < 4; i++) {
        int node = nbase + tr * 4 + i;
        if (node < NN) {
            int c = cnt[node];
            float inv = 1.f / fmaxf((float)c, 1.f);
            float bf = c > 0 ? 1.f : 0.f;
            float4 bv = *((const float4*)b1 + tc);
            *(float4*)&x[(size_t)node * 64 + tc * 4] = make_float4(
                acc[i][0] * inv + bv.x * bf, acc[i][1] * inv + bv.y * bf,
                acc[i][2] * inv + bv.z * bf, acc[i][3] * inv + bv.w * bf);
        }
    }
}

// ------------------------------------------------------------------
// edge_conv1 (fused, packed f32x2): per tile of 64 pairs,
//   OUT[64,128] = 0.5*Hsum@Wc + c0 + act*wl128 + ang*wl129   -> fe1
//   T  [64,128] = Hdiff@W1 ; lsum += ||T||^2
// smem float offsets:
#define EC1_WC   0
#define EC1_W1   16384
#define EC1_HST  32768      // Hsum^T [128][68]
#define EC1_HDT  41472      // Hdiff^T [128][68]
#define EC1_ACT  50176
#define EC1_ANG  50240
#define EC1_C0   50304
#define EC1_WLR  50432      // wl128[128] | wl129[128]
#define EC1_B0   50688
#define EC1_SPI  50816      // 64 ints
#define EC1_DPI  50880
#define EC1_RED  50944      // 16
#define EC1_TOT  50960
#define EC1_NTILE 12500

__global__ void __launch_bounds__(512) edge_conv1_kernel(
    const float* __restrict__ P, const int* __restrict__ ei,
    const float* __restrict__ act, const float* __restrict__ ang,
    const float* __restrict__ b0,
    const float* __restrict__ Wc, const float* __restrict__ c0,
    const float* __restrict__ Wl, const float* __restrict__ W1,
    float* __restrict__ fe1, double* __restrict__ lossp)
{
    extern __shared__ float sm[];
    float* WcS = sm + EC1_WC;
    float* W1S = sm + EC1_W1;
    float* HST = sm + EC1_HST;
    float* HDT = sm + EC1_HDT;
    float* ACT = sm + EC1_ACT;
    float* ANG = sm + EC1_ANG;
    float* C0S = sm + EC1_C0;
    float* WLR = sm + EC1_WLR;
    float* B0S = sm + EC1_B0;
    int* SP = (int*)(sm + EC1_SPI);
    int* DP = (int*)(sm + EC1_DPI);
    float* RED = sm + EC1_RED;
    const int tid = threadIdx.x;

    // resident weights
    for (int i = tid; i < 4096; i += 512) ((float4*)WcS)[i] = ((const float4*)Wc)[i];
    for (int i = tid; i < 4096; i += 512) ((float4*)W1S)[i] = ((const float4*)W1)[i];
    if (tid < 256) WLR[tid] = Wl[(128 + (tid >> 7)) * 128 + (tid & 127)];
    if (tid < 128) C0S[tid] = c0[tid];
    if (tid < 32)  ((float4*)B0S)[tid] = ((const float4*)b0)[tid];

    const int group = tid >> 8;           // 0: OUT gemm, 1: loss gemm
    const int sub = tid & 255;
    const int tr = sub >> 4, tc = sub & 15;
    float lsum = 0.f;

    for (int tile = blockIdx.x; tile < EC1_NTILE; tile += gridDim.x) {
        const int pbase = tile * 64;
        __syncthreads();
        if (tid < 64) {
            SP[tid] = ei[pbase + tid];
            DP[tid] = ei[NP + pbase + tid];
            ACT[tid] = act[pbase + tid];
            ANG[tid] = ang[pbase + tid];
        }
        __syncthreads();

        // build Hsum^T / Hdiff^T
#pragma unroll
        for (int it = 0; it < 4; it++) {
            int idx = tid + it * 512;
            int r = idx >> 5, c4 = idx & 31;
            int s = SP[r], d = DP[r];
            const float4* Ps = (const float4*)(P + (size_t)s * 256);
            const float4* Pd = (const float4*)(P + (size_t)d * 256);
            float4 a1 = __ldg(Ps + c4),      bb1 = __ldg(Pd + 32 + c4);
            float4 a2 = __ldg(Pd + c4),      bb2 = __ldg(Ps + 32 + c4);
            float4 b0v = *(const float4*)&B0S[c4 * 4];
            float h1, h2;
            h1 = lrelu(a1.x + bb1.x + b0v.x); h2 = lrelu(a2.x + bb2.x + b0v.x);
            HST[(c4 * 4 + 0) * 68 + r] = h1 + h2; HDT[(c4 * 4 + 0) * 68 + r] = h1 - h2;
            h1 = lrelu(a1.y + bb1.y + b0v.y); h2 = lrelu(a2.y + bb2.y + b0v.y);
            HST[(c4 * 4 + 1) * 68 + r] = h1 + h2; HDT[(c4 * 4 + 1) * 68 + r] = h1 - h2;
            h1 = lrelu(a1.z + bb1.z + b0v.z); h2 = lrelu(a2.z + bb2.z + b0v.z);
            HST[(c4 * 4 + 2) * 68 + r] = h1 + h2; HDT[(c4 * 4 + 2) * 68 + r] = h1 - h2;
            h1 = lrelu(a1.w + bb1.w + b0v.w); h2 = lrelu(a2.w + bb2.w + b0v.w);
            HST[(c4 * 4 + 3) * 68 + r] = h1 + h2; HDT[(c4 * 4 + 3) * 68 + r] = h1 - h2;
        }
        __syncthreads();

        // GEMM: [64,128] @ [128,128], packed f32x2
        const float* HS = group ? HDT : HST;
        const float* W  = group ? W1S : WcS;
        unsigned long long acc[4][4];
#pragma unroll
        for (int i = 0; i < 4; i++)
#pragma unroll
            for (int j = 0; j < 4; j++) acc[i][j] = 0ull;

#pragma unroll 8
        for (int k = 0; k < 128; k++) {
            float4 a = *(const float4*)&HS[k * 68 + tr * 4];
            const ulonglong2* wp = (const ulonglong2*)&W[k * 128 + tc * 8];
            ulonglong2 w01 = wp[0];
            ulonglong2 w23 = wp[1];
            unsigned long long a0 = pack2(a.x), a1 = pack2(a.y),
                               a2 = pack2(a.z), a3 = pack2(a.w);
            acc[0][0] = ffma2(a0, w01.x, acc[0][0]);
            acc[0][1] = ffma2(a0, w01.y, acc[0][1]);
            acc[0][2] = ffma2(a0, w23.x, acc[0][2]);
            acc[0][3] = ffma2(a0, w23.y, acc[0][3]);
            acc[1][0] = ffma2(a1, w01.x, acc[1][0]);
            acc[1][1] = ffma2(a1, w01.y, acc[1][1]);
            acc[1][2] = ffma2(a1, w23.x, acc[1][2]);
            acc[1][3] = ffma2(a1, w23.y, acc[1][3]);
            acc[2][0] = ffma2(a2, w01.x, acc[2][0]);
            acc[2][1] = ffma2(a2, w01.y, acc[2][1]);
            acc[2][2] = ffma2(a2, w23.x, acc[2][2]);
            acc[2][3] = ffma2(a2, w23.y, acc[2][3]);
            acc[3][0] = ffma2(a3, w01.x, acc[3][0]);
            acc[3][1] = ffma2(a3, w01.y, acc[3][1]);
            acc[3][2] = ffma2(a3, w23.x, acc[3][2]);
            acc[3][3] = ffma2(a3, w23.y, acc[3][3]);
        }

        if (group == 0) {
#pragma unroll
            for (int i = 0; i < 4; i++) {
                int p = tr * 4 + i;
                float av = ACT[p], gv = ANG[p];
                float o[8];
#pragma unroll
                for (int j = 0; j < 4; j++) unpack2(acc[i][j], o[2 * j], o[2 * j + 1]);
                float v[8];
#pragma unroll
                for (int j = 0; j < 8; j++) {
                    int c = tc * 8 + j;
                    v[j] = 0.5f * o[j] + C0S[c] + av * WLR[c] + gv * WLR[128 + c];
                }
                float4* dst = (float4*)&fe1[(size_t)(pbase + p) * 128 + tc * 8];
                dst[0] = make_float4(v[0], v[1], v[2], v[3]);
                dst[1] = make_float4(v[4], v[5], v[6], v[7]);
            }
        } else {
#pragma unroll
            for (int i = 0; i < 4; i++)
#pragma unroll
                for (int j = 0; j < 4; j++) {
                    float lo, hi;
                    unpack2(acc[i][j], lo, hi);
                    lsum += lo * lo + hi * hi;
                }
        }
    }

    // loss reduce
#pragma unroll
    for (int o = 16; o > 0; o >>= 1) lsum += __shfl_down_sync(0xffffffffu, lsum, o);
    __syncthreads();
    if ((tid & 31) == 0) RED[tid >> 5] = lsum;
    __syncthreads();
    if (tid == 0) {
        float t = 0.f;
#pragma unroll
        for (int w = 0; w < 16; w++) t += RED[w];
        atomicAdd(lossp, (double)t);
    }
}

// ------------------------------------------------------------------
// edge_conv2 (fused): per pair:
//   out3 = (h1+h2)@Wc2(0.5 folded) + fe1@WlB + c2 ; loss += ||(h1-h2)@W1e||^2
#define W9(k) ((k) * 12 + (((k) >> 5) << 2))

__global__ void __launch_bounds__(256) edge_conv2_kernel(
    const float* __restrict__ P, const int* __restrict__ ei,
    const float* __restrict__ fe1,
    const float* __restrict__ b0,
    const float* __restrict__ Wc2, const float* __restrict__ W1e,
    const float* __restrict__ Wl2, const float* __restrict__ c2,
    float* __restrict__ out, double* __restrict__ lossp)
{
    __shared__ float W9S[128 * 12 + 16];
    __shared__ float B0S[128];
    __shared__ float C2S[4];
    __shared__ float RED[8];
    const int tid = threadIdx.x;

    for (int i = tid; i < 1152; i += 256) {
        int k = i / 9, c = i % 9;
        float v = (c < 3) ? Wc2[k * 3 + c]
                : (c < 6) ? W1e[k * 3 + (c - 3)]
                          : Wl2[(3 + k) * 3 + (c - 6)];
        W9S[W9(k) + c] = v;
    }
    if (tid < 32) ((float4*)B0S)[tid] = ((const float4*)b0)[tid];
    if (tid < 3)  C2S[tid] = c2[tid];
    __syncthreads();

    const int p = tid >> 2, q = tid & 3;
    const int gp = blockIdx.x * 64 + p;
    const int s = ei[gp];
    const int d = ei[NP + gp];
    const float4* Ps = (const float4*)(P + (size_t)s * 256);
    const float4* Pd = (const float4*)(P + (size_t)d * 256);
    const float4* F4 = (const float4*)(fe1 + (size_t)gp * 128);

    float o0 = 0.f, o1 = 0.f, o2 = 0.f, t0 = 0.f, t1 = 0.f, t2 = 0.f;
    const int kb = q * 8;
#pragma unroll
    for (int c8 = 0; c8 < 8; c8++) {
        int c4 = kb + c8;
        float4 a1 = __ldg(Ps + c4),  bb1 = __ldg(Pd + 32 + c4);
        float4 a2 = __ldg(Pd + c4),  bb2 = __ldg(Ps + 32 + c4);
        float4 fv = __ldg(F4 + c4);
        float4 b0v = *(const float4*)&B0S[c4 * 4];
        float av1[4] = {a1.x, a1.y, a1.z, a1.w};
        float bv1[4] = {bb1.x, bb1.y, bb1.z, bb1.w};
        float av2[4] = {a2.x, a2.y, a2.z, a2.w};
        float bv2[4] = {bb2.x, bb2.y, bb2.z, bb2.w};
        float fvv[4] = {fv.x, fv.y, fv.z, fv.w};
        float b0a[4] = {b0v.x, b0v.y, b0v.z, b0v.w};
#pragma unroll
        for (int j = 0; j < 4; j++) {
            int k = c4 * 4 + j;
            float h1 = lrelu(av1[j] + bv1[j] + b0a[j]);
            float h2 = lrelu(av2[j] + bv2[j] + b0a[j]);
            float hs = h1 + h2, hd = h1 - h2, f = fvv[j];
            const float* w = &W9S[W9(k)];
            o0 += hs * w[0] + f * w[6];
            o1 += hs * w[1] + f * w[7];
            o2 += hs * w[2] + f * w[8];
            t0 += hd * w[3];
            t1 += hd * w[4];
            t2 += hd * w[5];
        }
    }
    // reduce across the 4 threads of this pair
#pragma unroll
    for (int off = 2; off > 0; off >>= 1) {
        o0 += __shfl_down_sync(0xffffffffu, o0, off, 4);
        o1 += __shfl_down_sync(0xffffffffu, o1, off, 4);
        o2 += __shfl_down_sync(0xffffffffu, o2, off, 4);
        t0 += __shfl_down_sync(0xffffffffu, t0, off, 4);
        t1 += __shfl_down_sync(0xffffffffu, t1, off, 4);
        t2 += __shfl_down_sync(0xffffffffu, t2, off, 4);
    }
    float lp = 0.f;
    if (q == 0) {
        out[(size_t)gp * 3 + 0] = o0 + C2S[0];
        out[(size_t)gp * 3 + 1] = o1 + C2S[1];
        out[(size_t)gp * 3 + 2] = o2 + C2S[2];
        lp = t0 * t0 + t1 * t1 + t2 * t2;
    }
#pragma unroll
    for (int o = 16; o > 0; o >>= 1) lp += __shfl_down_sync(0xffffffffu, lp, o);
    if ((tid & 31) == 0) RED[tid >> 5] = lp;
    __syncthreads();
    if (tid == 0) {
        float t = 0.f;
#pragma unroll
        for (int w = 0; w < 8; w++) t += RED[w];
        atomicAdd(lossp, (double)t);
    }
}

// ------------------------------------------------------------------
__global__ void finalize_kernel(float* __restrict__ out, int idx)
{
    double l = 0.5 * (g_loss[0] / (800000.0 * 128.0) + g_loss[1] / (800000.0 * 3.0));
    out[idx] = (float)l;
}

// ------------------------------------------------------------------
extern "C" void kernel_launch(void* const* d_in, const int* in_sizes, int n_in,
                              void* d_out, int out_size)
{
    (void)in_sizes; (void)n_in;
    const float* xnf  = (const float*)d_in[0];
    const int*   ei   = (const int*)d_in[1];
    const float* ang  = (const float*)d_in[2];
    const float* act  = (const float*)d_in[3];
    const float* nc1W0 = (const float*)d_in[5];
    const float* nc1b0 = (const float*)d_in[6];
    const float* nc1W1 = (const float*)d_in[7];
    const float* nc1b1 = (const float*)d_in[8];
    const float* ec1W0 = (const float*)d_in[9];
    const float* ec1b0 = (const float*)d_in[10];
    const float* ec1W1 = (const float*)d_in[11];
    const float* ec1b1 = (const float*)d_in[12];
    const float* ec1Wl = (const float*)d_in[13];
    const float* ec1bl = (const float*)d_in[14];
    const float* nc2W0 = (const float*)d_in[15];
    const float* nc2b0 = (const float*)d_in[16];
    const float* nc2W1 = (const float*)d_in[17];
    const float* nc2b1 = (const float*)d_in[18];
    const float* ec2W0 = (const float*)d_in[19];
    const float* ec2b0 = (const float*)d_in[20];
    const float* ec2W1 = (const float*)d_in[21];
    const float* ec2b1 = (const float*)d_in[22];
    const float* ec2Wl = (const float*)d_in[23];
    const float* ec2bl = (const float*)d_in[24];
    float* out = (float*)d_out;

    float *hagg, *x1, *x2, *fe1, *PA, *PB, *Wc, *c0, *Wc2, *c2;
    int* cnt;
    double* loss;
    cudaGetSymbolAddress((void**)&hagg, g_hagg);
    cudaGetSymbolAddress((void**)&x1,   g_x1);
    cudaGetSymbolAddress((void**)&x2,   g_x2);
    cudaGetSymbolAddress((void**)&fe1,  g_fe1);
    cudaGetSymbolAddress((void**)&PA,   g_PA);
    cudaGetSymbolAddress((void**)&PB,   g_PB);
    cudaGetSymbolAddress((void**)&Wc,   g_Wc);
    cudaGetSymbolAddress((void**)&c0,   g_c0);
    cudaGetSymbolAddress((void**)&Wc2,  g_Wc2);
    cudaGetSymbolAddress((void**)&c2,   g_c2);
    cudaGetSymbolAddress((void**)&cnt,  g_cnt);
    cudaGetSymbolAddress((void**)&loss, g_loss);

    static int attr_done = 0;
    if (!attr_done) {
        cudaFuncSetAttribute(edge_conv1_kernel,
                             cudaFuncAttributeMaxDynamicSharedMemorySize,
                             EC1_TOT * sizeof(float));
        attr_done = 1;
    }

    cudaMemsetAsync(hagg, 0, (size_t)NN * 128 * sizeof(float));
    cudaMemsetAsync(cnt, 0, (size_t)NN * sizeof(int));
    cudaMemsetAsync(loss, 0, 2 * sizeof(double));

    const int NB64 = (NN + 63) / 64;

    count_kernel<<<(NP + 255) / 256, 256>>>(ei, cnt);

    // weight fusions (independent)
    fuseA_kernel<<<64, 256>>>(ec1W1, ec1Wl, Wc);
    fuseA2_kernel<<<1, 128>>>(ec1Wl, ec1b1, ec1bl, c0);
    fuseB_kernel<<<1, 384>>>(ec2W1, ec2Wl, ec2b1, ec2bl, Wc2, c2);

    // ---- conv layer 1 (node) ----
    node_proj_kernel<<<NB64, 256>>>(xnf, nc1W0, PA);
    scatter_kernel<<<NE / 8, 256>>>(PA, ei, nc1b0, hagg);
    node_gemm_kernel<<<NB64, 256>>>(hagg, cnt, nc1W1, nc1b1, x1);

    // ---- edge conv 1 ----
    node_proj_kernel<<<NB64, 256>>>(x1, ec1W0, PB);
    edge_conv1_kernel<<<148, 512, EC1_TOT * sizeof(float)>>>(
        PB, ei, act, ang, ec1b0, Wc, c0, ec1Wl, ec1W1, fe1, loss);

    // ---- conv layer 2 (node) ----
    cudaMemsetAsync(hagg, 0, (size_t)NN * 128 * sizeof(float));
    node_proj_kernel<<<NB64, 256>>>(x1, nc2W0, PA);
    scatter_kernel<<<NE / 8, 256>>>(PA, ei, nc2b0, hagg);
    node_gemm_kernel<<<NB64, 256>>>(hagg, cnt, nc2W1, nc2b1, x2);

    // ---- edge conv 2 ----
    node_proj_kernel<<<NB64, 256>>>(x2, ec2W0, PA);
    edge_conv2_kernel<<<NP / 64, 256>>>(PA, ei, fe1, ec2b0,
                                        Wc2, ec2W1, ec2Wl, c2,
                                        out, loss + 1);
    finalize_kernel<<<1, 1>>>(out, out_size - 1);
}

// round 5
// speedup vs baseline: 6.1680x; 2.0481x over previous
#include <cuda_runtime.h>

#define NN 50000
#define NP 800000   // undirected pairs
#define NE 1600000  // directed edges

// ---------------- scratch (static device globals; no allocations) ----------------
__device__ float  g_x1[NN * 64];
__device__ float  g_x2[NN * 64];
__device__ float  g_hagg[NN * 128];
__device__ int    g_cnt[NN];
__device__ float  g_PA[NN * 256];
__device__ float  g_PB[NN * 256];
__device__ float  g_fe1[102400000];   // 800000 x 128
__device__ float  g_Wc[16384];        // W1 @ Wl[0:128]  (edge_conv1 fused)
__device__ float  g_c0[128];          // b1 @ Wl[0:128] + bl
__device__ float  g_Wc2[384];         // 0.5 * W1e2 @ Wl2[0:3]
__device__ float  g_c2[4];            // b1e2 @ Wl2[0:3] + bl2
__device__ double g_loss[2];

__device__ __forceinline__ float lrelu(float z) { return z > 0.f ? z : 0.01f * z; }

__device__ __forceinline__ unsigned tf32_bits(float x)
{
    unsigned r;
    asm("cvt.rna.tf32.f32 %0, %1;" : "=r"(r) : "f"(x));
    return r;
}

__device__ __forceinline__ void mma_tf32(float c[4],
    unsigned a0, unsigned a1, unsigned a2, unsigned a3,
    unsigned b0, unsigned b1)
{
    asm volatile(
        "mma.sync.aligned.m16n8k8.row.col.f32.tf32.tf32.f32 "
        "{%0,%1,%2,%3}, {%4,%5,%6,%7}, {%8,%9}, {%0,%1,%2,%3};"
        : "+f"(c[0]), "+f"(c[1]), "+f"(c[2]), "+f"(c[3])
        : "r"(a0), "r"(a1), "r"(a2), "r"(a3), "r"(b0), "r"(b1));
}

// ------------------------------------------------------------------
// Weight fusion precompute kernels
__global__ void fuseA_kernel(const float* __restrict__ W1, const float* __restrict__ Wl,
                             float* __restrict__ Wc)
{
    int id = blockIdx.x * 256 + threadIdx.x;   // 16384
    int r = id >> 7, c = id & 127;
    float s = 0.f;
#pragma unroll 8
    for (int k = 0; k < 128; k++) s += W1[r * 128 + k] * Wl[k * 128 + c];
    Wc[id] = s;
}
__global__ void fuseA2_kernel(const float* __restrict__ Wl, const float* __restrict__ b1,
                              const float* __restrict__ bl, float* __restrict__ c0)
{
    int c = threadIdx.x;   // 128
    float s = bl[c];
#pragma unroll 8
    for (int k = 0; k < 128; k++) s += b1[k] * Wl[k * 128 + c];
    c0[c] = s;
}
__global__ void fuseB_kernel(const float* __restrict__ W1e, const float* __restrict__ Wl2,
                             const float* __restrict__ b1, const float* __restrict__ bl,
                             float* __restrict__ Wc2, float* __restrict__ c2)
{
    int id = threadIdx.x;   // 384
    if (id < 384) {
        int k = id / 3, c = id % 3;
        Wc2[id] = 0.5f * (W1e[k * 3 + 0] * Wl2[0 + c] +
                          W1e[k * 3 + 1] * Wl2[3 + c] +
                          W1e[k * 3 + 2] * Wl2[6 + c]);
    }
    if (id < 3)
        c2[id] = b1[0] * Wl2[0 + id] + b1[1] * Wl2[3 + id] + b1[2] * Wl2[6 + id] + bl[id];
}

// ------------------------------------------------------------------
// P[n][0..127] = x[n] @ W0[0:64,:]  ; P[n][128..255] = x[n] @ W0[64:128,:]
__global__ void __launch_bounds__(256) node_proj_kernel(
    const float* __restrict__ x, const float* __restrict__ W0, float* __restrict__ P)
{
    __shared__ float XT[64 * 68];
    __shared__ float WC[16 * 256];
    const int tid = threadIdx.x;
    const int nbase = blockIdx.x * 64;
#pragma unroll
    for (int i = 0; i < 4; i++) {
        int lin = tid * 4 + i;
        int r = lin >> 4, q = lin & 15;
        int node = nbase + r; if (node >= NN) node = NN - 1;
        float4 v = __ldg((const float4*)x + (size_t)node * 16 + q);
        XT[(q * 4 + 0) * 68 + r] = v.x;
        XT[(q * 4 + 1) * 68 + r] = v.y;
        XT[(q * 4 + 2) * 68 + r] = v.z;
        XT[(q * 4 + 3) * 68 + r] = v.w;
    }
    float acc[8][8];
#pragma unroll
    for (int i = 0; i < 8; i++)
#pragma unroll
        for (int j = 0; j < 8; j++) acc[i][j] = 0.f;
    const int tr = tid >> 5, tc = tid & 31;
    for (int kc = 0; kc < 64; kc += 16) {
        __syncthreads();
#pragma unroll
        for (int i = 0; i < 4; i++) {
            int lin = tid + i * 256;
            int kk = lin >> 6, j4 = lin & 63;
            int j = j4 * 4;
            const float* src = (j < 128) ? (W0 + (kc + kk) * 128 + j)
                                         : (W0 + (64 + kc + kk) * 128 + (j - 128));
            *(float4*)&WC[kk * 256 + j] = *(const float4*)src;
        }
        __syncthreads();
#pragma unroll
        for (int kk = 0; kk < 16; kk++) {
            float4 a0 = *(const float4*)&XT[(kc + kk) * 68 + tr * 8];
            float4 a1 = *(const float4*)&XT[(kc + kk) * 68 + tr * 8 + 4];
            float4 w0 = *(const float4*)&WC[kk * 256 + tc * 8];
            float4 w1 = *(const float4*)&WC[kk * 256 + tc * 8 + 4];
            float a[8] = {a0.x, a0.y, a0.z, a0.w, a1.x, a1.y, a1.z, a1.w};
            float w[8] = {w0.x, w0.y, w0.z, w0.w, w1.x, w1.y, w1.z, w1.w};
#pragma unroll
            for (int i = 0; i < 8; i++)
#pragma unroll
                for (int j = 0; j < 8; j++) acc[i][j] += a[i] * w[j];
        }
    }
#pragma unroll
    for (int i = 0; i < 8; i++) {
        int node = nbase + tr * 8 + i;
        if (node < NN) {
            *(float4*)&P[(size_t)node * 256 + tc * 8] =
                make_float4(acc[i][0], acc[i][1], acc[i][2], acc[i][3]);
            *(float4*)&P[(size_t)node * 256 + tc * 8 + 4] =
                make_float4(acc[i][4], acc[i][5], acc[i][6], acc[i][7]);
        }
    }
}

// ------------------------------------------------------------------
__global__ void count_kernel(const int* __restrict__ ei, int* __restrict__ cnt)
{
    int j = blockIdx.x * blockDim.x + threadIdx.x;
    if (j < NP) {
        atomicAdd(&cnt[ei[j]], 1);
        atomicAdd(&cnt[ei[NP + j]], 1);
    }
}

// ------------------------------------------------------------------
// Per directed edge e: h = lrelu(Pt[src] + Pb[dst] + b0); Hagg[dst] += h  (v4 red)
__global__ void __launch_bounds__(256) scatter_kernel(
    const float* __restrict__ P, const int* __restrict__ ei,
    const float* __restrict__ b0, float* __restrict__ Hagg)
{
    const int tid = threadIdx.x;
    const int lane = tid & 31;
    const int e = (blockIdx.x * 256 + tid) >> 5;
    if (e >= NE) return;
    const int src = ei[e];
    const int dst = ei[NE + e];
    float4 a = __ldg((const float4*)(P + (size_t)src * 256) + lane);
    float4 b = __ldg((const float4*)(P + (size_t)dst * 256) + 32 + lane);
    float4 b0v = __ldg((const float4*)b0 + lane);
    float h0 = lrelu(a.x + b.x + b0v.x);
    float h1 = lrelu(a.y + b.y + b0v.y);
    float h2 = lrelu(a.z + b.z + b0v.z);
    float h3 = lrelu(a.w + b.w + b0v.w);
    float* dp = Hagg + (size_t)dst * 128 + lane * 4;
    asm volatile("red.global.add.v4.f32 [%0], {%1,%2,%3,%4};"
                 :: "l"(dp), "f"(h0), "f"(h1), "f"(h2), "f"(h3) : "memory");
}

// ------------------------------------------------------------------
// x[n] = (Hagg[n] @ W1)/max(cnt,1) + b1*(cnt>0)
__global__ void __launch_bounds__(256) node_gemm_kernel(
    const float* __restrict__ Hagg, const int* __restrict__ cnt,
    const float* __restrict__ W1, const float* __restrict__ b1,
    float* __restrict__ x)
{
    __shared__ float HT[128 * 68];
    __shared__ float W1S[32 * 64];
    const int tid = threadIdx.x;
    const int nbase = blockIdx.x * 64;
#pragma unroll
    for (int it = 0; it < 8; it++) {
        int lin = tid + it * 256;
        int n = lin >> 5, q = lin & 31;
        int node = nbase + n; if (node >= NN) node = NN - 1;
        float4 v = *((const float4*)(Hagg + (size_t)node * 128) + q);
        HT[(q * 4 + 0) * 68 + n] = v.x;
        HT[(q * 4 + 1) * 68 + n] = v.y;
        HT[(q * 4 + 2) * 68 + n] = v.z;
        HT[(q * 4 + 3) * 68 + n] = v.w;
    }
    float acc[4][4];
#pragma unroll
    for (int i = 0; i < 4; i++)
#pragma unroll
        for (int j = 0; j < 4; j++) acc[i][j] = 0.f;
    const int tr = tid >> 4, tc = tid & 15;
    for (int kc = 0; kc < 128; kc += 32) {
        __syncthreads();
#pragma unroll
        for (int t = 0; t < 2; t++) {
            int lin = tid + t * 256;
            int kk = lin >> 4, c4 = lin & 15;
            *(float4*)&W1S[kk * 64 + c4 * 4] = *(const float4*)(W1 + (kc + kk) * 64 + c4 * 4);
        }
        __syncthreads();
#pragma unroll
        for (int kk = 0; kk < 32; kk++) {
            float a0 = HT[(kc + kk) * 68 + tr * 4 + 0];
            float a1 = HT[(kc + kk) * 68 + tr * 4 + 1];
            float a2 = HT[(kc + kk) * 68 + tr * 4 + 2];
            float a3 = HT[(kc + kk) * 68 + tr * 4 + 3];
            float4 w = *(const float4*)&W1S[kk * 64 + tc * 4];
            acc[0][0] += a0 * w.x; acc[0][1] += a0 * w.y; acc[0][2] += a0 * w.z; acc[0][3] += a0 * w.w;
            acc[1][0] += a1 * w.x; acc[1][1] += a1 * w.y; acc[1][2] += a1 * w.z; acc[1][3] += a1 * w.w;
            acc[2][0] += a2 * w.x; acc[2][1] += a2 * w.y; acc[2][2] += a2 * w.z; acc[2][3] += a2 * w.w;
            acc[3][0] += a3 * w.x; acc[3][1] += a3 * w.y; acc[3][2] += a3 * w.z; acc[3][3] += a3 * w.w;
        }
    }
#pragma unroll
    for (int i = 0; i < 4; i++) {
        int node = nbase + tr * 4 + i;
        if (node < NN) {
            int c = cnt[node];
            float inv = 1.f / fmaxf((float)c, 1.f);
            float bf = c > 0 ? 1.f : 0.f;
            float4 bv = *((const float4*)b1 + tc);
            *(float4*)&x[(size_t)node * 64 + tc * 4] = make_float4(
                acc[i][0] * inv + bv.x * bf, acc[i][1] * inv + bv.y * bf,
                acc[i][2] * inv + bv.z * bf, acc[i][3] * inv + bv.w * bf);
        }
    }
}

// ------------------------------------------------------------------
// edge_conv1 (tf32 tensor cores): per tile of 64 pairs,
//   fe1[64,128] = 0.5*Hsum@Wc + c0 + act*wl128 + ang*wl129
//   loss += || Hdiff @ W1 ||^2
// smem float offsets:
#define EC1_WC   0          // [128][136] tf32
#define EC1_W1   17408      // [128][136] tf32
#define EC1_HS   34816      // [64][132] tf32 (Hsum)
#define EC1_HD   43264      // [64][132] tf32 (Hdiff)
#define EC1_ACT  51712
#define EC1_ANG  51776
#define EC1_C0   51840
#define EC1_WLR  51968      // wl row128[128] | row129[128]
#define EC1_B0   52224
#define EC1_SPI  52352      // 64 ints
#define EC1_DPI  52416
#define EC1_RED  52480      // 16
#define EC1_TOT  52496
#define EC1_NTILE 12500

__global__ void __launch_bounds__(512) edge_conv1_kernel(
    const float* __restrict__ P, const int* __restrict__ ei,
    const float* __restrict__ act, const float* __restrict__ ang,
    const float* __restrict__ b0,
    const float* __restrict__ Wc, const float* __restrict__ c0,
    const float* __restrict__ Wl, const float* __restrict__ W1,
    float* __restrict__ fe1, double* __restrict__ lossp)
{
    extern __shared__ float sm[];
    float* WcS = sm + EC1_WC;
    float* W1S = sm + EC1_W1;
    float* HS  = sm + EC1_HS;
    float* HD  = sm + EC1_HD;
    float* ACT = sm + EC1_ACT;
    float* ANG = sm + EC1_ANG;
    float* C0S = sm + EC1_C0;
    float* WLR = sm + EC1_WLR;
    float* B0S = sm + EC1_B0;
    int* SP = (int*)(sm + EC1_SPI);
    int* DP = (int*)(sm + EC1_DPI);
    float* RED = sm + EC1_RED;
    const int tid = threadIdx.x;

    // stage weights (tf32-rounded) once per block
    for (int i = tid; i < 16384; i += 512) {
        int k = i >> 7, n = i & 127;
        WcS[k * 136 + n] = __uint_as_float(tf32_bits(Wc[i]));
        W1S[k * 136 + n] = __uint_as_float(tf32_bits(W1[i]));
    }
    if (tid < 256) WLR[tid] = Wl[(128 + (tid >> 7)) * 128 + (tid & 127)];
    if (tid < 128) C0S[tid] = c0[tid];
    if (tid < 32)  ((float4*)B0S)[tid] = ((const float4*)b0)[tid];

    const int w = tid >> 5, lane = tid & 31;
    const int group = w >> 3, wi = w & 7;      // group 0: fe1 GEMM, 1: loss GEMM
    const int gid = lane >> 2, tig = lane & 3;
    const int m0 = (wi & 3) * 16, n0 = (wi >> 2) * 64;
    float lsum = 0.f;

    for (int tile = blockIdx.x; tile < EC1_NTILE; tile += gridDim.x) {
        const int pbase = tile * 64;
        __syncthreads();   // previous tile fully consumed
        if (tid < 64) {
            SP[tid] = ei[pbase + tid];
            DP[tid] = ei[NP + pbase + tid];
            ACT[tid] = act[pbase + tid];
            ANG[tid] = ang[pbase + tid];
        }
        __syncthreads();

        // build Hsum / Hdiff (row-major, tf32-rounded)
#pragma unroll
        for (int it = 0; it < 4; it++) {
            int idx = tid + it * 512;
            int r = idx >> 5, c4 = idx & 31;
            int s = SP[r], d = DP[r];
            const float4* Ps = (const float4*)(P + (size_t)s * 256);
            const float4* Pd = (const float4*)(P + (size_t)d * 256);
            float4 a1 = __ldg(Ps + c4),  bb1 = __ldg(Pd + 32 + c4);
            float4 a2 = __ldg(Pd + c4),  bb2 = __ldg(Ps + 32 + c4);
            float4 b0v = *(const float4*)&B0S[c4 * 4];
            float h1, h2;
            float4 hs, hd;
            h1 = lrelu(a1.x + bb1.x + b0v.x); h2 = lrelu(a2.x + bb2.x + b0v.x);
            hs.x = __uint_as_float(tf32_bits(h1 + h2)); hd.x = __uint_as_float(tf32_bits(h1 - h2));
            h1 = lrelu(a1.y + bb1.y + b0v.y); h2 = lrelu(a2.y + bb2.y + b0v.y);
            hs.y = __uint_as_float(tf32_bits(h1 + h2)); hd.y = __uint_as_float(tf32_bits(h1 - h2));
            h1 = lrelu(a1.z + bb1.z + b0v.z); h2 = lrelu(a2.z + bb2.z + b0v.z);
            hs.z = __uint_as_float(tf32_bits(h1 + h2)); hd.z = __uint_as_float(tf32_bits(h1 - h2));
            h1 = lrelu(a1.w + bb1.w + b0v.w); h2 = lrelu(a2.w + bb2.w + b0v.w);
            hs.w = __uint_as_float(tf32_bits(h1 + h2)); hd.w = __uint_as_float(tf32_bits(h1 - h2));
            *(float4*)&HS[r * 132 + c4 * 4] = hs;
            *(float4*)&HD[r * 132 + c4 * 4] = hd;
        }
        __syncthreads();

        // GEMM [64,128] @ [128,128] via m16n8k8 tf32 mma
        const float* A = group ? HD : HS;
        const float* W = group ? W1S : WcS;
        float c[8][4];
#pragma unroll
        for (int nt = 0; nt < 8; nt++)
#pragma unroll
            for (int j = 0; j < 4; j++) c[nt][j] = 0.f;

#pragma unroll 4
        for (int ks = 0; ks < 16; ks++) {
            int k = ks * 8;
            unsigned a0 = __float_as_uint(A[(m0 + gid) * 132 + k + tig]);
            unsigned a1 = __float_as_uint(A[(m0 + 8 + gid) * 132 + k + tig]);
            unsigned a2 = __float_as_uint(A[(m0 + gid) * 132 + k + 4 + tig]);
            unsigned a3 = __float_as_uint(A[(m0 + 8 + gid) * 132 + k + 4 + tig]);
#pragma unroll
            for (int nt = 0; nt < 8; nt++) {
                unsigned b0f = __float_as_uint(W[(k + tig) * 136 + n0 + nt * 8 + gid]);
                unsigned b1f = __float_as_uint(W[(k + 4 + tig) * 136 + n0 + nt * 8 + gid]);
                mma_tf32(c[nt], a0, a1, a2, a3, b0f, b1f);
            }
        }

        if (group == 0) {
            int p1 = m0 + gid, p2 = p1 + 8;
            float av1 = ACT[p1], gv1 = ANG[p1];
            float av2 = ACT[p2], gv2 = ANG[p2];
#pragma unroll
            for (int nt = 0; nt < 8; nt++) {
                int col = n0 + nt * 8 + 2 * tig;
                float c0a = C0S[col], c0b = C0S[col + 1];
                float wa0 = WLR[col], wa1 = WLR[col + 1];
                float wg0 = WLR[128 + col], wg1 = WLR[128 + col + 1];
                float2 v1, v2;
                v1.x = 0.5f * c[nt][0] + c0a + av1 * wa0 + gv1 * wg0;
                v1.y = 0.5f * c[nt][1] + c0b + av1 * wa1 + gv1 * wg1;
                v2.x = 0.5f * c[nt][2] + c0a + av2 * wa0 + gv2 * wg0;
                v2.y = 0.5f * c[nt][3] + c0b + av2 * wa1 + gv2 * wg1;
                *(float2*)&fe1[(size_t)(pbase + p1) * 128 + col] = v1;
                *(float2*)&fe1[(size_t)(pbase + p2) * 128 + col] = v2;
            }
        } else {
#pragma unroll
            for (int nt = 0; nt < 8; nt++)
#pragma unroll
                for (int j = 0; j < 4; j++) lsum += c[nt][j] * c[nt][j];
        }
    }

    // loss reduce (512 threads)
#pragma unroll
    for (int o = 16; o > 0; o >>= 1) lsum += __shfl_down_sync(0xffffffffu, lsum, o);
    __syncthreads();
    if ((tid & 31) == 0) RED[tid >> 5] = lsum;
    __syncthreads();
    if (tid == 0) {
        float t = 0.f;
#pragma unroll
        for (int ww = 0; ww < 16; ww++) t += RED[ww];
        atomicAdd(lossp, (double)t);
    }
}

// ------------------------------------------------------------------
// edge_conv2 (fused): per pair:
//   out3 = (h1+h2)@Wc2(0.5 folded) + fe1@WlB + c2 ; loss += ||(h1-h2)@W1e||^2
#define W9(k) ((k) * 12 + (((k) >> 5) << 2))

__global__ void __launch_bounds__(256) edge_conv2_kernel(
    const float* __restrict__ P, const int* __restrict__ ei,
    const float* __restrict__ fe1,
    const float* __restrict__ b0,
    const float* __restrict__ Wc2, const float* __restrict__ W1e,
    const float* __restrict__ Wl2, const float* __restrict__ c2,
    float* __restrict__ out, double* __restrict__ lossp)
{
    __shared__ float W9S[128 * 12 + 16];
    __shared__ float B0S[128];
    __shared__ float C2S[4];
    __shared__ float RED[8];
    const int tid = threadIdx.x;

    for (int i = tid; i < 1152; i += 256) {
        int k = i / 9, c = i % 9;
        float v = (c < 3) ? Wc2[k * 3 + c]
                : (c < 6) ? W1e[k * 3 + (c - 3)]
                          : Wl2[(3 + k) * 3 + (c - 6)];
        W9S[W9(k) + c] = v;
    }
    if (tid < 32) ((float4*)B0S)[tid] = ((const float4*)b0)[tid];
    if (tid < 3)  C2S[tid] = c2[tid];
    __syncthreads();

    const int p = tid >> 2, q = tid & 3;
    const int gp = blockIdx.x * 64 + p;
    const int s = ei[gp];
    const int d = ei[NP + gp];
    const float4* Ps = (const float4*)(P + (size_t)s * 256);
    const float4* Pd = (const float4*)(P + (size_t)d * 256);
    const float4* F4 = (const float4*)(fe1 + (size_t)gp * 128);

    float o0 = 0.f, o1 = 0.f, o2 = 0.f, t0 = 0.f, t1 = 0.f, t2 = 0.f;
    const int kb = q * 8;
#pragma unroll
    for (int c8 = 0; c8 < 8; c8++) {
        int c4 = kb + c8;
        float4 a1 = __ldg(Ps + c4),  bb1 = __ldg(Pd + 32 + c4);
        float4 a2 = __ldg(Pd + c4),  bb2 = __ldg(Ps + 32 + c4);
        float4 fv = __ldg(F4 + c4);
        float4 b0v = *(const float4*)&B0S[c4 * 4];
        float av1[4] = {a1.x, a1.y, a1.z, a1.w};
        float bv1[4] = {bb1.x, bb1.y, bb1.z, bb1.w};
        float av2[4] = {a2.x, a2.y, a2.z, a2.w};
        float bv2[4] = {bb2.x, bb2.y, bb2.z, bb2.w};
        float fvv[4] = {fv.x, fv.y, fv.z, fv.w};
        float b0a[4] = {b0v.x, b0v.y, b0v.z, b0v.w};
#pragma unroll
        for (int j = 0; j < 4; j++) {
            int k = c4 * 4 + j;
            float h1 = lrelu(av1[j] + bv1[j] + b0a[j]);
            float h2 = lrelu(av2[j] + bv2[j] + b0a[j]);
            float hs = h1 + h2, hd = h1 - h2, f = fvv[j];
            const float* wv = &W9S[W9(k)];
            o0 += hs * wv[0] + f * wv[6];
            o1 += hs * wv[1] + f * wv[7];
            o2 += hs * wv[2] + f * wv[8];
            t0 += hd * wv[3];
            t1 += hd * wv[4];
            t2 += hd * wv[5];
        }
    }
#pragma unroll
    for (int off = 2; off > 0; off >>= 1) {
        o0 += __shfl_down_sync(0xffffffffu, o0, off, 4);
        o1 += __shfl_down_sync(0xffffffffu, o1, off, 4);
        o2 += __shfl_down_sync(0xffffffffu, o2, off, 4);
        t0 += __shfl_down_sync(0xffffffffu, t0, off, 4);
        t1 += __shfl_down_sync(0xffffffffu, t1, off, 4);
        t2 += __shfl_down_sync(0xffffffffu, t2, off, 4);
    }
    float lp = 0.f;
    if (q == 0) {
        out[(size_t)gp * 3 + 0] = o0 + C2S[0];
        out[(size_t)gp * 3 + 1] = o1 + C2S[1];
        out[(size_t)gp * 3 + 2] = o2 + C2S[2];
        lp = t0 * t0 + t1 * t1 + t2 * t2;
    }
#pragma unroll
    for (int o = 16; o > 0; o >>= 1) lp += __shfl_down_sync(0xffffffffu, lp, o);
    if ((tid & 31) == 0) RED[tid >> 5] = lp;
    __syncthreads();
    if (tid == 0) {
        float t = 0.f;
#pragma unroll
        for (int ww = 0; ww < 8; ww++) t += RED[ww];
        atomicAdd(lossp, (double)t);
    }
}

// ------------------------------------------------------------------
__global__ void finalize_kernel(float* __restrict__ out, int idx)
{
    double l = 0.5 * (g_loss[0] / (800000.0 * 128.0) + g_loss[1] / (800000.0 * 3.0));
    out[idx] = (float)l;
}

// ------------------------------------------------------------------
extern "C" void kernel_launch(void* const* d_in, const int* in_sizes, int n_in,
                              void* d_out, int out_size)
{
    (void)in_sizes; (void)n_in;
    const float* xnf  = (const float*)d_in[0];
    const int*   ei   = (const int*)d_in[1];
    const float* ang  = (const float*)d_in[2];
    const float* act  = (const float*)d_in[3];
    const float* nc1W0 = (const float*)d_in[5];
    const float* nc1b0 = (const float*)d_in[6];
    const float* nc1W1 = (const float*)d_in[7];
    const float* nc1b1 = (const float*)d_in[8];
    const float* ec1W0 = (const float*)d_in[9];
    const float* ec1b0 = (const float*)d_in[10];
    const float* ec1W1 = (const float*)d_in[11];
    const float* ec1b1 = (const float*)d_in[12];
    const float* ec1Wl = (const float*)d_in[13];
    const float* ec1bl = (const float*)d_in[14];
    const float* nc2W0 = (const float*)d_in[15];
    const float* nc2b0 = (const float*)d_in[16];
    const float* nc2W1 = (const float*)d_in[17];
    const float* nc2b1 = (const float*)d_in[18];
    const float* ec2W0 = (const float*)d_in[19];
    const float* ec2b0 = (const float*)d_in[20];
    const float* ec2W1 = (const float*)d_in[21];
    const float* ec2b1 = (const float*)d_in[22];
    const float* ec2Wl = (const float*)d_in[23];
    const float* ec2bl = (const float*)d_in[24];
    float* out = (float*)d_out;

    float *hagg, *x1, *x2, *fe1, *PA, *PB, *Wc, *c0, *Wc2, *c2;
    int* cnt;
    double* loss;
    cudaGetSymbolAddress((void**)&hagg, g_hagg);
    cudaGetSymbolAddress((void**)&x1,   g_x1);
    cudaGetSymbolAddress((void**)&x2,   g_x2);
    cudaGetSymbolAddress((void**)&fe1,  g_fe1);
    cudaGetSymbolAddress((void**)&PA,   g_PA);
    cudaGetSymbolAddress((void**)&PB,   g_PB);
    cudaGetSymbolAddress((void**)&Wc,   g_Wc);
    cudaGetSymbolAddress((void**)&c0,   g_c0);
    cudaGetSymbolAddress((void**)&Wc2,  g_Wc2);
    cudaGetSymbolAddress((void**)&c2,   g_c2);
    cudaGetSymbolAddress((void**)&cnt,  g_cnt);
    cudaGetSymbolAddress((void**)&loss, g_loss);

    static int attr_done = 0;
    if (!attr_done) {
        cudaFuncSetAttribute(edge_conv1_kernel,
                             cudaFuncAttributeMaxDynamicSharedMemorySize,
                             EC1_TOT * sizeof(float));
        attr_done = 1;
    }

    cudaMemsetAsync(hagg, 0, (size_t)NN * 128 * sizeof(float));
    cudaMemsetAsync(cnt, 0, (size_t)NN * sizeof(int));
    cudaMemsetAsync(loss, 0, 2 * sizeof(double));

    const int NB64 = (NN + 63) / 64;

    count_kernel<<<(NP + 255) / 256, 256>>>(ei, cnt);

    // weight fusions (independent)
    fuseA_kernel<<<64, 256>>>(ec1W1, ec1Wl, Wc);
    fuseA2_kernel<<<1, 128>>>(ec1Wl, ec1b1, ec1bl, c0);
    fuseB_kernel<<<1, 384>>>(ec2W1, ec2Wl, ec2b1, ec2bl, Wc2, c2);

    // ---- conv layer 1 (node) ----
    node_proj_kernel<<<NB64, 256>>>(xnf, nc1W0, PA);
    scatter_kernel<<<NE / 8, 256>>>(PA, ei, nc1b0, hagg);
    node_gemm_kernel<<<NB64, 256>>>(hagg, cnt, nc1W1, nc1b1, x1);

    // ---- edge conv 1 ----
    node_proj_kernel<<<NB64, 256>>>(x1, ec1W0, PB);
    edge_conv1_kernel<<<148, 512, EC1_TOT * sizeof(float)>>>(
        PB, ei, act, ang, ec1b0, Wc, c0, ec1Wl, ec1W1, fe1, loss);

    // ---- conv layer 2 (node) ----
    cudaMemsetAsync(hagg, 0, (size_t)NN * 128 * sizeof(float));
    node_proj_kernel<<<NB64, 256>>>(x1, nc2W0, PA);
    scatter_kernel<<<NE / 8, 256>>>(PA, ei, nc2b0, hagg);
    node_gemm_kernel<<<NB64, 256>>>(hagg, cnt, nc2W1, nc2b1, x2);

    // ---- edge conv 2 ----
    node_proj_kernel<<<NB64, 256>>>(x2, ec2W0, PA);
    edge_conv2_kernel<<<NP / 64, 256>>>(PA, ei, fe1, ec2b0,
                                        Wc2, ec2W1, ec2Wl, c2,
                                        out, loss + 1);
    finalize_kernel<<<1, 1>>>(out, out_size - 1);
}

// round 8
// speedup vs baseline: 6.9527x; 1.1272x over previous
#include <cuda_runtime.h>

#define NN 50000
#define NP 800000   // undirected pairs
#define NE 1600000  // directed edges

// ---------------- scratch (static device globals; no allocations) ----------------
__device__ float  g_x1[NN * 64];
__device__ float  g_x2[NN * 64];
__device__ float  g_hagg[NN * 128];
__device__ int    g_cnt[NN];
__device__ float  g_PA[NN * 256];
__device__ float  g_PB[NN * 256];
__device__ float  g_Wc[16384];        // ec1: W1 @ Wl[0:128]
__device__ float  g_c0[128];          // ec1: b1 @ Wl[0:128] + bl
__device__ float  g_Wc2[384];         // ec2: 0.5 * W1e2 @ Wl2[0:3]
__device__ float  g_c2[4];            // ec2: b1e2 @ Wl2[0:3] + bl2
__device__ float  g_Wcc[384];         // 0.5 * Wc @ WlB   (fe1 folded into ec2)
__device__ float  g_wa3[4];           // wl128 @ WlB
__device__ float  g_wg3[4];           // wl129 @ WlB
__device__ float  g_cc[4];            // c0 @ WlB + c2
__device__ double g_loss[2];

__device__ __forceinline__ float lrelu(float z) { return z > 0.f ? z : 0.01f * z; }

__device__ __forceinline__ unsigned tf32_bits(float x)
{
    unsigned r;
    asm("cvt.rna.tf32.f32 %0, %1;" : "=r"(r) : "f"(x));
    return r;
}

__device__ __forceinline__ void mma_tf32(float c[4],
    unsigned a0, unsigned a1, unsigned a2, unsigned a3,
    unsigned b0, unsigned b1)
{
    asm volatile(
        "mma.sync.aligned.m16n8k8.row.col.f32.tf32.tf32.f32 "
        "{%0,%1,%2,%3}, {%4,%5,%6,%7}, {%8,%9}, {%0,%1,%2,%3};"
        : "+f"(c[0]), "+f"(c[1]), "+f"(c[2]), "+f"(c[3])
        : "r"(a0), "r"(a1), "r"(a2), "r"(a3), "r"(b0), "r"(b1));
}

// ---------------- packed f32x2 helpers ----------------
__device__ __forceinline__ unsigned long long pack2(float x)
{
    unsigned long long r;
    asm("mov.b64 %0, {%1, %1};" : "=l"(r) : "f"(x));
    return r;
}
__device__ __forceinline__ unsigned long long ffma2(
    unsigned long long a, unsigned long long b, unsigned long long c)
{
    unsigned long long d;
    asm("fma.rn.f32x2 %0, %1, %2, %3;" : "=l"(d) : "l"(a), "l"(b), "l"(c));
    return d;
}
__device__ __forceinline__ void unpack2(unsigned long long v, float& lo, float& hi)
{
    asm("mov.b64 {%0, %1}, %2;" : "=f"(lo), "=f"(hi) : "l"(v));
}

// ------------------------------------------------------------------
// Weight fusion precompute kernels (run once per call, tiny)
__global__ void fuseA_kernel(const float* __restrict__ W1, const float* __restrict__ Wl,
                             float* __restrict__ Wc)
{
    int id = blockIdx.x * 256 + threadIdx.x;   // 16384
    int r = id >> 7, c = id & 127;
    float s = 0.f;
#pragma unroll 8
    for (int k = 0; k < 128; k++) s += W1[r * 128 + k] * Wl[k * 128 + c];
    Wc[id] = s;
}
__global__ void fuseA2_kernel(const float* __restrict__ Wl, const float* __restrict__ b1,
                              const float* __restrict__ bl, float* __restrict__ c0)
{
    int c = threadIdx.x;   // 128
    float s = bl[c];
#pragma unroll 8
    for (int k = 0; k < 128; k++) s += b1[k] * Wl[k * 128 + c];
    c0[c] = s;
}
__global__ void fuseB_kernel(const float* __restrict__ W1e, const float* __restrict__ Wl2,
                             const float* __restrict__ b1, const float* __restrict__ bl,
                             float* __restrict__ Wc2, float* __restrict__ c2)
{
    int id = threadIdx.x;   // 384
    if (id < 384) {
        int k = id / 3, c = id % 3;
        Wc2[id] = 0.5f * (W1e[k * 3 + 0] * Wl2[0 + c] +
                          W1e[k * 3 + 1] * Wl2[3 + c] +
                          W1e[k * 3 + 2] * Wl2[6 + c]);
    }
    if (id < 3)
        c2[id] = b1[0] * Wl2[0 + id] + b1[1] * Wl2[3 + id] + b1[2] * Wl2[6 + id] + bl[id];
}
// Wcc = 0.5 * Wc @ WlB ; wa3/wg3 = Wl rows 128/129 @ WlB ; cc = c0 @ WlB + c2
__global__ void fuseC_kernel(const float* __restrict__ Wc, const float* __restrict__ c0,
                             const float* __restrict__ Wl1, const float* __restrict__ Wl2,
                             const float* __restrict__ c2,
                             float* __restrict__ Wcc, float* __restrict__ wa3,
                             float* __restrict__ wg3, float* __restrict__ cc)
{
    int id = threadIdx.x;   // 384
    int k = id / 3, c = id % 3;
    float s = 0.f;
#pragma unroll 8
    for (int j = 0; j < 128; j++) s += Wc[k * 128 + j] * Wl2[(3 + j) * 3 + c];
    Wcc[id] = 0.5f * s;
    if (id < 3) {
        float sa = 0.f, sg = 0.f, sc = 0.f;
        for (int j = 0; j < 128; j++) {
            float wb = Wl2[(3 + j) * 3 + id];
            sa += Wl1[128 * 128 + j] * wb;
            sg += Wl1[129 * 128 + j] * wb;
            sc += c0[j] * wb;
        }
        wa3[id] = sa; wg3[id] = sg; cc[id] = sc + c2[id];
    }
}

// ------------------------------------------------------------------
// P[n][0..127] = x[n] @ W0[0:64,:]  ; P[n][128..255] = x[n] @ W0[64:128,:]
// packed f32x2 inner loop
__global__ void __launch_bounds__(256) node_proj_kernel(
    const float* __restrict__ x, const float* __restrict__ W0, float* __restrict__ P)
{
    __shared__ float XT[64 * 68];
    __shared__ float WC[16 * 256];
    const int tid = threadIdx.x;
    const int nbase = blockIdx.x * 64;
#pragma unroll
    for (int i = 0; i < 4; i++) {
        int lin = tid * 4 + i;
        int r = lin >> 4, q = lin & 15;
        int node = nbase + r; if (node >= NN) node = NN - 1;
        float4 v = __ldg((const float4*)x + (size_t)node * 16 + q);
        XT[(q * 4 + 0) * 68 + r] = v.x;
        XT[(q * 4 + 1) * 68 + r] = v.y;
        XT[(q * 4 + 2) * 68 + r] = v.z;
        XT[(q * 4 + 3) * 68 + r] = v.w;
    }
    unsigned long long acc2[8][4];
#pragma unroll
    for (int i = 0; i < 8; i++)
#pragma unroll
        for (int j = 0; j < 4; j++) acc2[i][j] = 0ull;
    const int tr = tid >> 5, tc = tid & 31;
    for (int kc = 0; kc < 64; kc += 16) {
        __syncthreads();
#pragma unroll
        for (int i = 0; i < 4; i++) {
            int lin = tid + i * 256;
            int kk = lin >> 6, j4 = lin & 63;
            int j = j4 * 4;
            const float* src = (j < 128) ? (W0 + (kc + kk) * 128 + j)
                                         : (W0 + (64 + kc + kk) * 128 + (j - 128));
            *(float4*)&WC[kk * 256 + j] = *(const float4*)src;
        }
        __syncthreads();
#pragma unroll
        for (int kk = 0; kk < 16; kk++) {
            float4 a0 = *(const float4*)&XT[(kc + kk) * 68 + tr * 8];
            float4 a1 = *(const float4*)&XT[(kc + kk) * 68 + tr * 8 + 4];
            ulonglong2 w01 = *(const ulonglong2*)&WC[kk * 256 + tc * 8];
            ulonglong2 w23 = *(const ulonglong2*)&WC[kk * 256 + tc * 8 + 4];
            float a[8] = {a0.x, a0.y, a0.z, a0.w, a1.x, a1.y, a1.z, a1.w};
#pragma unroll
            for (int i = 0; i < 8; i++) {
                unsigned long long ap = pack2(a[i]);
                acc2[i][0] = ffma2(ap, w01.x, acc2[i][0]);
                acc2[i][1] = ffma2(ap, w01.y, acc2[i][1]);
                acc2[i][2] = ffma2(ap, w23.x, acc2[i][2]);
                acc2[i][3] = ffma2(ap, w23.y, acc2[i][3]);
            }
        }
    }
#pragma unroll
    for (int i = 0; i < 8; i++) {
        int node = nbase + tr * 8 + i;
        if (node < NN) {
            float o[8];
#pragma unroll
            for (int j = 0; j < 4; j++) unpack2(acc2[i][j], o[2 * j], o[2 * j + 1]);
            *(float4*)&P[(size_t)node * 256 + tc * 8]     = make_float4(o[0], o[1], o[2], o[3]);
            *(float4*)&P[(size_t)node * 256 + tc * 8 + 4] = make_float4(o[4], o[5], o[6], o[7]);
        }
    }
}

// ------------------------------------------------------------------
__global__ void count_kernel(const int* __restrict__ ei, int* __restrict__ cnt)
{
    int j = blockIdx.x * blockDim.x + threadIdx.x;
    if (j < NP) {
        atomicAdd(&cnt[ei[j]], 1);
        atomicAdd(&cnt[ei[NP + j]], 1);
    }
}

// ------------------------------------------------------------------
// Per directed edge e: h = lrelu(Pt[src] + Pb[dst] + b0); Hagg[dst] += h  (v4 red)
__global__ void __launch_bounds__(256) scatter_kernel(
    const float* __restrict__ P, const int* __restrict__ ei,
    const float* __restrict__ b0, float* __restrict__ Hagg)
{
    const int tid = threadIdx.x;
    const int lane = tid & 31;
    const int e = (blockIdx.x * 256 + tid) >> 5;
    if (e >= NE) return;
    const int src = ei[e];
    const int dst = ei[NE + e];
    float4 a = __ldg((const float4*)(P + (size_t)src * 256) + lane);
    float4 b = __ldg((const float4*)(P + (size_t)dst * 256) + 32 + lane);
    float4 b0v = __ldg((const float4*)b0 + lane);
    float h0 = lrelu(a.x + b.x + b0v.x);
    float h1 = lrelu(a.y + b.y + b0v.y);
    float h2 = lrelu(a.z + b.z + b0v.z);
    float h3 = lrelu(a.w + b.w + b0v.w);
    float* dp = Hagg + (size_t)dst * 128 + lane * 4;
    asm volatile("red.global.add.v4.f32 [%0], {%1,%2,%3,%4};"
                 :: "l"(dp), "f"(h0), "f"(h1), "f"(h2), "f"(h3) : "memory");
}

// ------------------------------------------------------------------
// x[n] = (Hagg[n] @ W1)/max(cnt,1) + b1*(cnt>0)
__global__ void __launch_bounds__(256) node_gemm_kernel(
    const float* __restrict__ Hagg, const int* __restrict__ cnt,
    const float* __restrict__ W1, const float* __restrict__ b1,
    float* __restrict__ x)
{
    __shared__ float HT[128 * 68];
    __shared__ float W1S[32 * 64];
    const int tid = threadIdx.x;
    const int nbase = blockIdx.x * 64;
#pragma unroll
    for (int it = 0; it < 8; it++) {
        int lin = tid + it * 256;
        int n = lin >> 5, q = lin & 31;
        int node = nbase + n; if (node >= NN) node = NN - 1;
        float4 v = *((const float4*)(Hagg + (size_t)node * 128) + q);
        HT[(q * 4 + 0) * 68 + n] = v.x;
        HT[(q * 4 + 1) * 68 + n] = v.y;
        HT[(q * 4 + 2) * 68 + n] = v.z;
        HT[(q * 4 + 3) * 68 + n] = v.w;
    }
    float acc[4][4];
#pragma unroll
    for (int i = 0; i < 4; i++)
#pragma unroll
        for (int j = 0; j < 4; j++) acc[i][j] = 0.f;
    const int tr = tid >> 4, tc = tid & 15;
    for (int kc = 0; kc < 128; kc += 32) {
        __syncthreads();
#pragma unroll
        for (int t = 0; t < 2; t++) {
            int lin = tid + t * 256;
            int kk = lin >> 4, c4 = lin & 15;
            *(float4*)&W1S[kk * 64 + c4 * 4] = *(const float4*)(W1 + (kc + kk) * 64 + c4 * 4);
        }
        __syncthreads();
#pragma unroll
        for (int kk = 0; kk < 32; kk++) {
            float a0 = HT[(kc + kk) * 68 + tr * 4 + 0];
            float a1 = HT[(kc + kk) * 68 + tr * 4 + 1];
            float a2 = HT[(kc + kk) * 68 + tr * 4 + 2];
            float a3 = HT[(kc + kk) * 68 + tr * 4 + 3];
            float4 w = *(const float4*)&W1S[kk * 64 + tc * 4];
            acc[0][0] += a0 * w.x; acc[0][1] += a0 * w.y; acc[0][2] += a0 * w.z; acc[0][3] += a0 * w.w;
            acc[1][0] += a1 * w.x; acc[1][1] += a1 * w.y; acc[1][2] += a1 * w.z; acc[1][3] += a1 * w.w;
            acc[2][0] += a2 * w.x; acc[2][1] += a2 * w.y; acc[2][2] += a2 * w.z; acc[2][3] += a2 * w.w;
            acc[3][0] += a3 * w.x; acc[3][1] += a3 * w.y; acc[3][2] += a3 * w.z; acc[3][3] += a3 * w.w;
        }
    }
#pragma unroll
    for (int i = 0; i < 4; i++) {
        int node = nbase + tr * 4 + i;
        if (node < NN) {
            int c = cnt[node];
            float inv = 1.f / fmaxf((float)c, 1.f);
            float bf = c > 0 ? 1.f : 0.f;
            float4 bv = *((const float4*)b1 + tc);
            *(float4*)&x[(size_t)node * 64 + tc * 4] = make_float4(
                acc[i][0] * inv + bv.x * bf, acc[i][1] * inv + bv.y * bf,
                acc[i][2] * inv + bv.z * bf, acc[i][3] * inv + bv.w * bf);
        }
    }
}

// ------------------------------------------------------------------
// merged edge kernel: per tile of 64 pairs
//   build HS1 (fp32) / HD1 (tf32) from PB (ec1 hidden sums/diffs)
//   warps 8-15: loss1 += ||HD1 @ W1ec1||^2  (tf32 MMA)
//   warps 0-7 : per pair — gather PA2, hs2/hd2 matvecs + hs1@Wcc:
//               out3 = hs2@Wc2 + hs1@Wcc + act*wa3 + ang*wg3 + cc
//               loss2 += ||hd2@W1e2||^2
#define EF_W1   0
#define EF_HD1  17408
#define EF_HS1  25856
#define EF_W12  34304
#define EF_B0A  35872
#define EF_B0B  36000
#define EF_WA3  36128
#define EF_WG3  36132
#define EF_CCV  36136
#define EF_SPI  36160
#define EF_DPI  36224
#define EF_RED  36288
#define EF_TOT  36304
#define EF_NTILE 12500
#define W12(k) ((k) * 12 + (((k) >> 5) << 2))

__global__ void __launch_bounds__(512) edge_fused_kernel(
    const float* __restrict__ PB, const float* __restrict__ PA2,
    const int* __restrict__ ei,
    const float* __restrict__ act, const float* __restrict__ ang,
    const float* __restrict__ b0B, const float* __restrict__ b0A,
    const float* __restrict__ W1,
    const float* __restrict__ Wc2, const float* __restrict__ W1e2,
    const float* __restrict__ Wcc,
    const float* __restrict__ wa3, const float* __restrict__ wg3,
    const float* __restrict__ ccv,
    float* __restrict__ out, double* __restrict__ lossp)
{
    extern __shared__ float sm[];
    float* W1S = sm + EF_W1;     // [128][136] tf32
    float* HD1 = sm + EF_HD1;    // [64][132] tf32
    float* HS1 = sm + EF_HS1;    // [64][132] fp32
    float* W12S = sm + EF_W12;   // 128 x 12 (9 used) skewed
    float* B0A = sm + EF_B0A;
    float* B0B = sm + EF_B0B;
    float* WA3 = sm + EF_WA3;
    float* WG3 = sm + EF_WG3;
    float* CCV = sm + EF_CCV;
    int* SP = (int*)(sm + EF_SPI);
    int* DP = (int*)(sm + EF_DPI);
    float* RED = sm + EF_RED;
    const int tid = threadIdx.x;

    // stage weights once
    for (int i = tid; i < 16384; i += 512) {
        int k = i >> 7, n = i & 127;
        W1S[k * 136 + n] = __uint_as_float(tf32_bits(W1[i]));
    }
    for (int i = tid; i < 1152; i += 512) {
        int k = i / 9, c = i % 9;
        float v = (c < 3) ? Wc2[k * 3 + c]
                : (c < 6) ? W1e2[k * 3 + (c - 3)]
                          : Wcc[k * 3 + (c - 6)];
        W12S[W12(k) + c] = v;
    }
    if (tid < 32) ((float4*)B0A)[tid] = ((const float4*)b0A)[tid];
    else if (tid < 64) ((float4*)B0B)[tid - 32] = ((const float4*)b0B)[tid - 32];
    if (tid < 3) { WA3[tid] = wa3[tid]; WG3[tid] = wg3[tid]; CCV[tid] = ccv[tid]; }

    const int w = tid >> 5, lane = tid & 31;
    const int group = w >> 3;                 // 0: matvec warps, 1: MMA warps
    const int wi = w & 7, gid = lane >> 2, tig = lane & 3;
    const int m0 = (wi & 3) * 16, n0 = (wi >> 2) * 64;
    const int p = (tid & 255) >> 2, q = tid & 3;
    float lsum = 0.f;

    for (int tile = blockIdx.x; tile < EF_NTILE; tile += gridDim.x) {
        const int pbase = tile * 64;
        __syncthreads();   // previous tile fully consumed
        if (tid < 64) {
            SP[tid] = ei[pbase + tid];
            DP[tid] = ei[NP + pbase + tid];
        }
        __syncthreads();

        // build HS1 / HD1 from PB (all 512 threads)
#pragma unroll
        for (int it = 0; it < 4; it++) {
            int idx = tid + it * 512;
            int r = idx >> 5, c4 = idx & 31;
            int s = SP[r], d = DP[r];
            const float4* Ps = (const float4*)(PB + (size_t)s * 256);
            const float4* Pd = (const float4*)(PB + (size_t)d * 256);
            float4 a1 = __ldg(Ps + c4),  bb1 = __ldg(Pd + 32 + c4);
            float4 a2 = __ldg(Pd + c4),  bb2 = __ldg(Ps + 32 + c4);
            float4 b0v = *(const float4*)&B0B[c4 * 4];
            float h1, h2;
            float4 hs, hd;
            h1 = lrelu(a1.x + bb1.x + b0v.x); h2 = lrelu(a2.x + bb2.x + b0v.x);
            hs.x = h1 + h2; hd.x = __uint_as_float(tf32_bits(h1 - h2));
            h1 = lrelu(a1.y + bb1.y + b0v.y); h2 = lrelu(a2.y + bb2.y + b0v.y);
            hs.y = h1 + h2; hd.y = __uint_as_float(tf32_bits(h1 - h2));
            h1 = lrelu(a1.z + bb1.z + b0v.z); h2 = lrelu(a2.z + bb2.z + b0v.z);
            hs.z = h1 + h2; hd.z = __uint_as_float(tf32_bits(h1 - h2));
            h1 = lrelu(a1.w + bb1.w + b0v.w); h2 = lrelu(a2.w + bb2.w + b0v.w);
            hs.w = h1 + h2; hd.w = __uint_as_float(tf32_bits(h1 - h2));
            *(float4*)&HS1[r * 132 + c4 * 4] = hs;
            *(float4*)&HD1[r * 132 + c4 * 4] = hd;
        }
        __syncthreads();

        if (group == 1) {
            // loss1 GEMM: HD1[64,128] @ W1[128,128], square-sum
            float c[8][4];
#pragma unroll
            for (int nt = 0; nt < 8; nt++)
#pragma unroll
                for (int j = 0; j < 4; j++) c[nt][j] = 0.f;
#pragma unroll 4
            for (int ks = 0; ks < 16; ks++) {
                int k = ks * 8;
                unsigned a0 = __float_as_uint(HD1[(m0 + gid) * 132 + k + tig]);
                unsigned a1 = __float_as_uint(HD1[(m0 + 8 + gid) * 132 + k + tig]);
                unsigned a2 = __float_as_uint(HD1[(m0 + gid) * 132 + k + 4 + tig]);
                unsigned a3 = __float_as_uint(HD1[(m0 + 8 + gid) * 132 + k + 4 + tig]);
#pragma unroll
                for (int nt = 0; nt < 8; nt++) {
                    unsigned b0f = __float_as_uint(W1S[(k + tig) * 136 + n0 + nt * 8 + gid]);
                    unsigned b1f = __float_as_uint(W1S[(k + 4 + tig) * 136 + n0 + nt * 8 + gid]);
                    mma_tf32(c[nt], a0, a1, a2, a3, b0f, b1f);
                }
            }
#pragma unroll
            for (int nt = 0; nt < 8; nt++)
#pragma unroll
                for (int j = 0; j < 4; j++) lsum += c[nt][j] * c[nt][j];
        } else {
            // per-pair matvec path
            const int gp = pbase + p;
            const int s = SP[p], d = DP[p];
            const float4* Ps = (const float4*)(PA2 + (size_t)s * 256);
            const float4* Pd = (const float4*)(PA2 + (size_t)d * 256);
            float o0 = 0.f, o1 = 0.f, o2 = 0.f, t0 = 0.f, t1 = 0.f, t2 = 0.f;
#pragma unroll
            for (int c8 = 0; c8 < 8; c8++) {
                int c4 = q * 8 + c8;
                float4 a1 = __ldg(Ps + c4),  bb1 = __ldg(Pd + 32 + c4);
                float4 a2 = __ldg(Pd + c4),  bb2 = __ldg(Ps + 32 + c4);
                float4 hv = *(const float4*)&HS1[p * 132 + c4 * 4];
                float4 b0v = *(const float4*)&B0A[c4 * 4];
                float av1[4] = {a1.x, a1.y, a1.z, a1.w};
                float bv1[4] = {bb1.x, bb1.y, bb1.z, bb1.w};
                float av2[4] = {a2.x, a2.y, a2.z, a2.w};
                float bv2[4] = {bb2.x, bb2.y, bb2.z, bb2.w};
                float hsv[4] = {hv.x, hv.y, hv.z, hv.w};
                float b0a[4] = {b0v.x, b0v.y, b0v.z, b0v.w};
#pragma unroll
                for (int j = 0; j < 4; j++) {
                    int k = c4 * 4 + j;
                    float h1 = lrelu(av1[j] + bv1[j] + b0a[j]);
                    float h2 = lrelu(av2[j] + bv2[j] + b0a[j]);
                    float hs = h1 + h2, hd = h1 - h2, f = hsv[j];
                    const float* wv = &W12S[W12(k)];
                    o0 += hs * wv[0] + f * wv[6];
                    o1 += hs * wv[1] + f * wv[7];
                    o2 += hs * wv[2] + f * wv[8];
                    t0 += hd * wv[3];
                    t1 += hd * wv[4];
                    t2 += hd * wv[5];
                }
            }
#pragma unroll
            for (int off = 2; off > 0; off >>= 1) {
                o0 += __shfl_down_sync(0xffffffffu, o0, off, 4);
                o1 += __shfl_down_sync(0xffffffffu, o1, off, 4);
                o2 += __shfl_down_sync(0xffffffffu, o2, off, 4);
                t0 += __shfl_down_sync(0xffffffffu, t0, off, 4);
                t1 += __shfl_down_sync(0xffffffffu, t1, off, 4);
                t2 += __shfl_down_sync(0xffffffffu, t2, off, 4);
            }
            if (q == 0) {
                float av = __ldg(act + gp), gv = __ldg(ang + gp);
                out[(size_t)gp * 3 + 0] = o0 + av * WA3[0] + gv * WG3[0] + CCV[0];
                out[(size_t)gp * 3 + 1] = o1 + av * WA3[1] + gv * WG3[1] + CCV[1];
                out[(size_t)gp * 3 + 2] = o2 + av * WA3[2] + gv * WG3[2] + CCV[2];
                lsum += t0 * t0 + t1 * t1 + t2 * t2;
            }
        }
    }

    // final loss reduce: warps 0-7 hold loss2, warps 8-15 hold loss1
#pragma unroll
    for (int o = 16; o > 0; o >>= 1) lsum += __shfl_down_sync(0xffffffffu, lsum, o);
    __syncthreads();
    if (lane == 0) RED[w] = lsum;
    __syncthreads();
    if (tid == 0) {
        float l2 = 0.f, l1 = 0.f;
#pragma unroll
        for (int ww = 0; ww < 8; ww++)  l2 += RED[ww];
#pragma unroll
        for (int ww = 8; ww < 16; ww++) l1 += RED[ww];
        atomicAdd(&lossp[0], (double)l1);
        atomicAdd(&lossp[1], (double)l2);
    }
}

// ------------------------------------------------------------------
__global__ void finalize_kernel(float* __restrict__ out, int idx)
{
    double l = 0.5 * (g_loss[0] / (800000.0 * 128.0) + g_loss[1] / (800000.0 * 3.0));
    out[idx] = (float)l;
}

// ------------------------------------------------------------------
extern "C" void kernel_launch(void* const* d_in, const int* in_sizes, int n_in,
                              void* d_out, int out_size)
{
    (void)in_sizes; (void)n_in;
    const float* xnf  = (const float*)d_in[0];
    const int*   ei   = (const int*)d_in[1];
    const float* ang  = (const float*)d_in[2];
    const float* act  = (const float*)d_in[3];
    const float* nc1W0 = (const float*)d_in[5];
    const float* nc1b0 = (const float*)d_in[6];
    const float* nc1W1 = (const float*)d_in[7];
    const float* nc1b1 = (const float*)d_in[8];
    const float* ec1W0 = (const float*)d_in[9];
    const float* ec1b0 = (const float*)d_in[10];
    const float* ec1W1 = (const float*)d_in[11];
    const float* ec1b1 = (const float*)d_in[12];
    const float* ec1Wl = (const float*)d_in[13];
    const float* ec1bl = (const float*)d_in[14];
    const float* nc2W0 = (const float*)d_in[15];
    const float* nc2b0 = (const float*)d_in[16];
    const float* nc2W1 = (const float*)d_in[17];
    const float* nc2b1 = (const float*)d_in[18];
    const float* ec2W0 = (const float*)d_in[19];
    const float* ec2b0 = (const float*)d_in[20];
    const float* ec2W1 = (const float*)d_in[21];
    const float* ec2b1 = (const float*)d_in[22];
    const float* ec2Wl = (const float*)d_in[23];
    const float* ec2bl = (const float*)d_in[24];
    float* out = (float*)d_out;

    float *hagg, *x1, *x2, *PA, *PB, *Wc, *c0, *Wc2, *c2, *Wcc, *wa3, *wg3, *cc;
    int* cnt;
    double* loss;
    cudaGetSymbolAddress((void**)&hagg, g_hagg);
    cudaGetSymbolAddress((void**)&x1,   g_x1);
    cudaGetSymbolAddress((void**)&x2,   g_x2);
    cudaGetSymbolAddress((void**)&PA,   g_PA);
    cudaGetSymbolAddress((void**)&PB,   g_PB);
    cudaGetSymbolAddress((void**)&Wc,   g_Wc);
    cudaGetSymbolAddress((void**)&c0,   g_c0);
    cudaGetSymbolAddress((void**)&Wc2,  g_Wc2);
    cudaGetSymbolAddress((void**)&c2,   g_c2);
    cudaGetSymbolAddress((void**)&Wcc,  g_Wcc);
    cudaGetSymbolAddress((void**)&wa3,  g_wa3);
    cudaGetSymbolAddress((void**)&wg3,  g_wg3);
    cudaGetSymbolAddress((void**)&cc,   g_cc);
    cudaGetSymbolAddress((void**)&cnt,  g_cnt);
    cudaGetSymbolAddress((void**)&loss, g_loss);

    // Set the smem attribute ONCE, outside graph capture (first call is the
    // pre-capture correctness run). Calling this during capture is the prime
    // suspect for the R6/R7 container failures.
    static int attr_done = 0;
    if (!attr_done) {
        cudaFuncSetAttribute(edge_fused_kernel,
                             cudaFuncAttributeMaxDynamicSharedMemorySize,
                             EF_TOT * sizeof(float));
        attr_done = 1;
    }

    cudaMemsetAsync(hagg, 0, (size_t)NN * 128 * sizeof(float));
    cudaMemsetAsync(cnt, 0, (size_t)NN * sizeof(int));
    cudaMemsetAsync(loss, 0, 2 * sizeof(double));

    const int NB64 = (NN + 63) / 64;

    count_kernel<<<(NP + 255) / 256, 256>>>(ei, cnt);

    // weight fusions (C depends on A/A2/B; stream-ordered)
    fuseA_kernel<<<64, 256>>>(ec1W1, ec1Wl, Wc);
    fuseA2_kernel<<<1, 128>>>(ec1Wl, ec1b1, ec1bl, c0);
    fuseB_kernel<<<1, 384>>>(ec2W1, ec2Wl, ec2b1, ec2bl, Wc2, c2);
    fuseC_kernel<<<1, 384>>>(Wc, c0, ec1Wl, ec2Wl, c2, Wcc, wa3, wg3, cc);

    // ---- conv layer 1 (node) ----
    node_proj_kernel<<<NB64, 256>>>(xnf, nc1W0, PA);
    scatter_kernel<<<NE / 8, 256>>>(PA, ei, nc1b0, hagg);
    node_gemm_kernel<<<NB64, 256>>>(hagg, cnt, nc1W1, nc1b1, x1);

    // ---- projection for edge conv 1 ----
    node_proj_kernel<<<NB64, 256>>>(x1, ec1W0, PB);

    // ---- conv layer 2 (node) ----
    cudaMemsetAsync(hagg, 0, (size_t)NN * 128 * sizeof(float));
    node_proj_kernel<<<NB64, 256>>>(x1, nc2W0, PA);
    scatter_kernel<<<NE / 8, 256>>>(PA, ei, nc2b0, hagg);
    node_gemm_kernel<<<NB64, 256>>>(hagg, cnt, nc2W1, nc2b1, x2);

    // ---- projection for edge conv 2 ----
    node_proj_kernel<<<NB64, 256>>>(x2, ec2W0, PA);

    // ---- merged edge convs ----
    edge_fused_kernel<<<148, 512, EF_TOT * sizeof(float)>>>(
        PB, PA, ei, act, ang, ec1b0, ec2b0, ec1W1,
        Wc2, ec2W1, Wcc, wa3, wg3, cc, out, loss);

    finalize_kernel<<<1, 1>>>(out, out_size - 1);
}

// round 9
// speedup vs baseline: 9.8565x; 1.4177x over previous
#include <cuda_runtime.h>
#include <cuda_fp16.h>

#define NN 50000
#define NP 800000   // undirected pairs
#define NE 1600000  // directed edges

// ---------------- scratch (static device globals; no allocations) ----------------
__device__ float  g_x1[NN * 64];
__device__ float  g_x2[NN * 64];
__device__ float  g_hagg[NN * 128];
__device__ int    g_cnt[NN];
__device__ int    g_offs[NN + 1];
__device__ int    g_cur[NN];
__device__ int    g_srcs[NE];
__device__ float  g_PA[NN * 256];     // fp32 conv projections; reused as half for PA2
__device__ float  g_PB[NN * 256];     // reused as half table for edge conv 1
__device__ float  g_Wc[16384];        // ec1: W1 @ Wl[0:128]
__device__ float  g_c0[128];          // ec1: b1 @ Wl[0:128] + bl
__device__ float  g_Wc2[384];         // ec2: 0.5 * W1e2 @ Wl2[0:3]
__device__ float  g_c2[4];            // ec2: b1e2 @ Wl2[0:3] + bl2
__device__ float  g_Wcc[384];         // 0.5 * Wc @ WlB   (fe1 folded into ec2)
__device__ float  g_wa3[4];           // wl128 @ WlB
__device__ float  g_wg3[4];           // wl129 @ WlB
__device__ float  g_cc[4];            // c0 @ WlB + c2
__device__ double g_loss[2];

__device__ __forceinline__ float lrelu(float z) { return z > 0.f ? z : 0.01f * z; }

__device__ __forceinline__ unsigned tf32_bits(float x)
{
    unsigned r;
    asm("cvt.rna.tf32.f32 %0, %1;" : "=r"(r) : "f"(x));
    return r;
}

__device__ __forceinline__ void mma_tf32(float c[4],
    unsigned a0, unsigned a1, unsigned a2, unsigned a3,
    unsigned b0, unsigned b1)
{
    asm volatile(
        "mma.sync.aligned.m16n8k8.row.col.f32.tf32.tf32.f32 "
        "{%0,%1,%2,%3}, {%4,%5,%6,%7}, {%8,%9}, {%0,%1,%2,%3};"
        : "+f"(c[0]), "+f"(c[1]), "+f"(c[2]), "+f"(c[3])
        : "r"(a0), "r"(a1), "r"(a2), "r"(a3), "r"(b0), "r"(b1));
}

// ---------------- packed f32x2 helpers ----------------
__device__ __forceinline__ unsigned long long pack2(float x)
{
    unsigned long long r;
    asm("mov.b64 %0, {%1, %1};" : "=l"(r) : "f"(x));
    return r;
}
__device__ __forceinline__ unsigned long long ffma2(
    unsigned long long a, unsigned long long b, unsigned long long c)
{
    unsigned long long d;
    asm("fma.rn.f32x2 %0, %1, %2, %3;" : "=l"(d) : "l"(a), "l"(b), "l"(c));
    return d;
}
__device__ __forceinline__ void unpack2(unsigned long long v, float& lo, float& hi)
{
    asm("mov.b64 {%0, %1}, %2;" : "=f"(lo), "=f"(hi) : "l"(v));
}

// half4 (uint2) -> 4 floats
__device__ __forceinline__ void h4_to_f4(uint2 u, float& f0, float& f1, float& f2, float& f3)
{
    __half2 p01 = *(__half2*)&u.x;
    __half2 p23 = *(__half2*)&u.y;
    float2 a = __half22float2(p01);
    float2 b = __half22float2(p23);
    f0 = a.x; f1 = a.y; f2 = b.x; f3 = b.y;
}

// ------------------------------------------------------------------
// Weight fusion precompute kernels (run once per call, tiny)
__global__ void fuseA_kernel(const float* __restrict__ W1, const float* __restrict__ Wl,
                             float* __restrict__ Wc)
{
    int id = blockIdx.x * 256 + threadIdx.x;   // 16384
    int r = id >> 7, c = id & 127;
    float s = 0.f;
#pragma unroll 8
    for (int k = 0; k < 128; k++) s += W1[r * 128 + k] * Wl[k * 128 + c];
    Wc[id] = s;
}
__global__ void fuseA2_kernel(const float* __restrict__ Wl, const float* __restrict__ b1,
                              const float* __restrict__ bl, float* __restrict__ c0)
{
    int c = threadIdx.x;   // 128
    float s = bl[c];
#pragma unroll 8
    for (int k = 0; k < 128; k++) s += b1[k] * Wl[k * 128 + c];
    c0[c] = s;
}
__global__ void fuseB_kernel(const float* __restrict__ W1e, const float* __restrict__ Wl2,
                             const float* __restrict__ b1, const float* __restrict__ bl,
                             float* __restrict__ Wc2, float* __restrict__ c2)
{
    int id = threadIdx.x;   // 384
    if (id < 384) {
        int k = id / 3, c = id % 3;
        Wc2[id] = 0.5f * (W1e[k * 3 + 0] * Wl2[0 + c] +
                          W1e[k * 3 + 1] * Wl2[3 + c] +
                          W1e[k * 3 + 2] * Wl2[6 + c]);
    }
    if (id < 3)
        c2[id] = b1[0] * Wl2[0 + id] + b1[1] * Wl2[3 + id] + b1[2] * Wl2[6 + id] + bl[id];
}
// Wcc = 0.5 * Wc @ WlB ; wa3/wg3 = Wl rows 128/129 @ WlB ; cc = c0 @ WlB + c2
__global__ void fuseC_kernel(const float* __restrict__ Wc, const float* __restrict__ c0,
                             const float* __restrict__ Wl1, const float* __restrict__ Wl2,
                             const float* __restrict__ c2,
                             float* __restrict__ Wcc, float* __restrict__ wa3,
                             float* __restrict__ wg3, float* __restrict__ cc)
{
    int id = threadIdx.x;   // 384
    int k = id / 3, c = id % 3;
    float s = 0.f;
#pragma unroll 8
    for (int j = 0; j < 128; j++) s += Wc[k * 128 + j] * Wl2[(3 + j) * 3 + c];
    Wcc[id] = 0.5f * s;
    if (id < 3) {
        float sa = 0.f, sg = 0.f, sc = 0.f;
        for (int j = 0; j < 128; j++) {
            float wb = Wl2[(3 + j) * 3 + id];
            sa += Wl1[128 * 128 + j] * wb;
            sg += Wl1[129 * 128 + j] * wb;
            sc += c0[j] * wb;
        }
        wa3[id] = sa; wg3[id] = sg; cc[id] = sc + c2[id];
    }
}

// ------------------------------------------------------------------
// CSR build: count (dst degrees) -> scan -> fill
__global__ void count_kernel(const int* __restrict__ ei, int* __restrict__ cnt)
{
    int e = blockIdx.x * blockDim.x + threadIdx.x;
    if (e < NE) atomicAdd(&cnt[ei[NE + e]], 1);
}

__global__ void __launch_bounds__(1024) scan_kernel(const int* __restrict__ cnt,
                                                    int* __restrict__ offs)
{
    __shared__ int part[1024];
    const int t = threadIdx.x;
    const int CH = (NN + 1023) / 1024;   // 49
    const int base = t * CH;
    int s = 0;
    for (int j = 0; j < CH; j++) {
        int n = base + j;
        if (n < NN) s += cnt[n];
    }
    part[t] = s;
    __syncthreads();
    // Hillis-Steele inclusive scan
    for (int off = 1; off < 1024; off <<= 1) {
        int v = (t >= off) ? part[t - off] : 0;
        __syncthreads();
        part[t] += v;
        __syncthreads();
    }
    int run = part[t] - s;   // exclusive base of this chunk
    for (int j = 0; j < CH; j++) {
        int n = base + j;
        if (n < NN) { offs[n] = run; run += cnt[n]; }
    }
    if (t == 1023) offs[NN] = part[1023];
}

__global__ void fill_kernel(const int* __restrict__ ei, const int* __restrict__ offs,
                            int* __restrict__ cur, int* __restrict__ srcs)
{
    int e = blockIdx.x * blockDim.x + threadIdx.x;
    if (e < NE) {
        int src = ei[e];
        int dst = ei[NE + e];
        int pos = atomicAdd(&cur[dst], 1);
        srcs[offs[dst] + pos] = src;
    }
}

// ------------------------------------------------------------------
// node_proj: P[n][0..127] = x[n] @ W0[0:64,:] ; P[n][128..255] = x[n] @ W0[64:128,:]
// HALF_OUT: write __half table (for edge_fused gathers)
template <bool HALF_OUT>
__global__ void __launch_bounds__(256) node_proj_kernel(
    const float* __restrict__ x, const float* __restrict__ W0, void* __restrict__ Pout)
{
    __shared__ float XT[64 * 68];
    __shared__ float WC[16 * 256];
    const int tid = threadIdx.x;
    const int nbase = blockIdx.x * 64;
#pragma unroll
    for (int i = 0; i < 4; i++) {
        int lin = tid * 4 + i;
        int r = lin >> 4, q = lin & 15;
        int node = nbase + r; if (node >= NN) node = NN - 1;
        float4 v = __ldg((const float4*)x + (size_t)node * 16 + q);
        XT[(q * 4 + 0) * 68 + r] = v.x;
        XT[(q * 4 + 1) * 68 + r] = v.y;
        XT[(q * 4 + 2) * 68 + r] = v.z;
        XT[(q * 4 + 3) * 68 + r] = v.w;
    }
    unsigned long long acc2[8][4];
#pragma unroll
    for (int i = 0; i < 8; i++)
#pragma unroll
        for (int j = 0; j < 4; j++) acc2[i][j] = 0ull;
    const int tr = tid >> 5, tc = tid & 31;
    for (int kc = 0; kc < 64; kc += 16) {
        __syncthreads();
#pragma unroll
        for (int i = 0; i < 4; i++) {
            int lin = tid + i * 256;
            int kk = lin >> 6, j4 = lin & 63;
            int j = j4 * 4;
            const float* src = (j < 128) ? (W0 + (kc + kk) * 128 + j)
                                         : (W0 + (64 + kc + kk) * 128 + (j - 128));
            *(float4*)&WC[kk * 256 + j] = *(const float4*)src;
        }
        __syncthreads();
#pragma unroll
        for (int kk = 0; kk < 16; kk++) {
            float4 a0 = *(const float4*)&XT[(kc + kk) * 68 + tr * 8];
            float4 a1 = *(const float4*)&XT[(kc + kk) * 68 + tr * 8 + 4];
            ulonglong2 w01 = *(const ulonglong2*)&WC[kk * 256 + tc * 8];
            ulonglong2 w23 = *(const ulonglong2*)&WC[kk * 256 + tc * 8 + 4];
            float a[8] = {a0.x, a0.y, a0.z, a0.w, a1.x, a1.y, a1.z, a1.w};
#pragma unroll
            for (int i = 0; i < 8; i++) {
                unsigned long long ap = pack2(a[i]);
                acc2[i][0] = ffma2(ap, w01.x, acc2[i][0]);
                acc2[i][1] = ffma2(ap, w01.y, acc2[i][1]);
                acc2[i][2] = ffma2(ap, w23.x, acc2[i][2]);
                acc2[i][3] = ffma2(ap, w23.y, acc2[i][3]);
            }
        }
    }
#pragma unroll
    for (int i = 0; i < 8; i++) {
        int node = nbase + tr * 8 + i;
        if (node < NN) {
            float o[8];
#pragma unroll
            for (int j = 0; j < 4; j++) unpack2(acc2[i][j], o[2 * j], o[2 * j + 1]);
            if (HALF_OUT) {
                __half* Ph = (__half*)Pout;
                __half2 h0 = __floats2half2_rn(o[0], o[1]);
                __half2 h1 = __floats2half2_rn(o[2], o[3]);
                __half2 h2 = __floats2half2_rn(o[4], o[5]);
                __half2 h3 = __floats2half2_rn(o[6], o[7]);
                uint4 v;
                v.x = *(unsigned*)&h0; v.y = *(unsigned*)&h1;
                v.z = *(unsigned*)&h2; v.w = *(unsigned*)&h3;
                *(uint4*)&Ph[(size_t)node * 256 + tc * 8] = v;
            } else {
                float* P = (float*)Pout;
                *(float4*)&P[(size_t)node * 256 + tc * 8]     = make_float4(o[0], o[1], o[2], o[3]);
                *(float4*)&P[(size_t)node * 256 + tc * 8 + 4] = make_float4(o[4], o[5], o[6], o[7]);
            }
        }
    }
}

// ------------------------------------------------------------------
// CSR aggregation: Hagg[n] = sum over in-edges (src->n) of lrelu(Pt[src]+Pb[n]+b0)
// warp per node; lane owns one float4 column chunk.
__global__ void __launch_bounds__(256) aggregate_kernel(
    const float* __restrict__ P, const int* __restrict__ offs,
    const int* __restrict__ srcs, const float* __restrict__ b0,
    float* __restrict__ Hagg)
{
    const int n = blockIdx.x * 8 + (threadIdx.x >> 5);
    const int lane = threadIdx.x & 31;
    if (n >= NN) return;
    const float4* P4 = (const float4*)P;
    float4 pb = __ldg(P4 + (size_t)n * 64 + 32 + lane);
    float4 b0v = __ldg((const float4*)b0 + lane);
    pb.x += b0v.x; pb.y += b0v.y; pb.z += b0v.z; pb.w += b0v.w;
    const int beg = offs[n], end = offs[n + 1];
    float4 acc = make_float4(0.f, 0.f, 0.f, 0.f);
    int i = beg;
    for (; i + 4 <= end; i += 4) {
        int s0 = srcs[i], s1 = srcs[i + 1], s2 = srcs[i + 2], s3 = srcs[i + 3];
        float4 a0 = __ldg(P4 + (size_t)s0 * 64 + lane);
        float4 a1 = __ldg(P4 + (size_t)s1 * 64 + lane);
        float4 a2 = __ldg(P4 + (size_t)s2 * 64 + lane);
        float4 a3 = __ldg(P4 + (size_t)s3 * 64 + lane);
        acc.x += lrelu(a0.x + pb.x) + lrelu(a1.x + pb.x) + lrelu(a2.x + pb.x) + lrelu(a3.x + pb.x);
        acc.y += lrelu(a0.y + pb.y) + lrelu(a1.y + pb.y) + lrelu(a2.y + pb.y) + lrelu(a3.y + pb.y);
        acc.z += lrelu(a0.z + pb.z) + lrelu(a1.z + pb.z) + lrelu(a2.z + pb.z) + lrelu(a3.z + pb.z);
        acc.w += lrelu(a0.w + pb.w) + lrelu(a1.w + pb.w) + lrelu(a2.w + pb.w) + lrelu(a3.w + pb.w);
    }
    for (; i < end; i++) {
        int s = srcs[i];
        float4 a = __ldg(P4 + (size_t)s * 64 + lane);
        acc.x += lrelu(a.x + pb.x);
        acc.y += lrelu(a.y + pb.y);
        acc.z += lrelu(a.z + pb.z);
        acc.w += lrelu(a.w + pb.w);
    }
    ((float4*)Hagg)[(size_t)n * 32 + lane] = acc;
}

// ------------------------------------------------------------------
// x[n] = (Hagg[n] @ W1)/max(deg,1) + b1*(deg>0)
__global__ void __launch_bounds__(256) node_gemm_kernel(
    const float* __restrict__ Hagg, const int* __restrict__ offs,
    const float* __restrict__ W1, const float* __restrict__ b1,
    float* __restrict__ x)
{
    __shared__ float HT[128 * 68];
    __shared__ float W1S[32 * 64];
    const int tid = threadIdx.x;
    const int nbase = blockIdx.x * 64;
#pragma unroll
    for (int it = 0; it < 8; it++) {
        int lin = tid + it * 256;
        int n = lin >> 5, q = lin & 31;
        int node = nbase + n; if (node >= NN) node = NN - 1;
        float4 v = *((const float4*)(Hagg + (size_t)node * 128) + q);
        HT[(q * 4 + 0) * 68 + n] = v.x;
        HT[(q * 4 + 1) * 68 + n] = v.y;
        HT[(q * 4 + 2) * 68 + n] = v.z;
        HT[(q * 4 + 3) * 68 + n] = v.w;
    }
    float acc[4][4];
#pragma unroll
    for (int i = 0; i < 4; i++)
#pragma unroll
        for (int j = 0; j < 4; j++) acc[i][j] = 0.f;
    const int tr = tid >> 4, tc = tid & 15;
    for (int kc = 0; kc < 128; kc += 32) {
        __syncthreads();
#pragma unroll
        for (int t = 0; t < 2; t++) {
            int lin = tid + t * 256;
            int kk = lin >> 4, c4 = lin & 15;
            *(float4*)&W1S[kk * 64 + c4 * 4] = *(const float4*)(W1 + (kc + kk) * 64 + c4 * 4);
        }
        __syncthreads();
#pragma unroll
        for (int kk = 0; kk < 32; kk++) {
            float a0 = HT[(kc + kk) * 68 + tr * 4 + 0];
            float a1 = HT[(kc + kk) * 68 + tr * 4 + 1];
            float a2 = HT[(kc + kk) * 68 + tr * 4 + 2];
            float a3 = HT[(kc + kk) * 68 + tr * 4 + 3];
            float4 w = *(const float4*)&W1S[kk * 64 + tc * 4];
            acc[0][0] += a0 * w.x; acc[0][1] += a0 * w.y; acc[0][2] += a0 * w.z; acc[0][3] += a0 * w.w;
            acc[1][0] += a1 * w.x; acc[1][1] += a1 * w.y; acc[1][2] += a1 * w.z; acc[1][3] += a1 * w.w;
            acc[2][0] += a2 * w.x; acc[2][1] += a2 * w.y; acc[2][2] += a2 * w.z; acc[2][3] += a2 * w.w;
            acc[3][0] += a3 * w.x; acc[3][1] += a3 * w.y; acc[3][2] += a3 * w.z; acc[3][3] += a3 * w.w;
        }
    }
#pragma unroll
    for (int i = 0; i < 4; i++) {
        int node = nbase + tr * 4 + i;
        if (node < NN) {
            int deg = offs[node + 1] - offs[node];
            float inv = 1.f / fmaxf((float)deg, 1.f);
            float bf = deg > 0 ? 1.f : 0.f;
            float4 bv = *((const float4*)b1 + tc);
            *(float4*)&x[(size_t)node * 64 + tc * 4] = make_float4(
                acc[i][0] * inv + bv.x * bf, acc[i][1] * inv + bv.y * bf,
                acc[i][2] * inv + bv.z * bf, acc[i][3] * inv + bv.w * bf);
        }
    }
}

// ------------------------------------------------------------------
// merged edge kernel: per tile of 64 pairs (P tables in fp16)
#define EF_W1   0
#define EF_HD1  17408
#define EF_HS1  25856
#define EF_W12  34304
#define EF_B0A  35872
#define EF_B0B  36000
#define EF_WA3  36128
#define EF_WG3  36132
#define EF_CCV  36136
#define EF_SPI  36160
#define EF_DPI  36224
#define EF_RED  36288
#define EF_TOT  36304
#define EF_NTILE 12500
#define W12(k) ((k) * 12 + (((k) >> 5) << 2))

__global__ void __launch_bounds__(512) edge_fused_kernel(
    const __half* __restrict__ PB, const __half* __restrict__ PA2,
    const int* __restrict__ ei,
    const float* __restrict__ act, const float* __restrict__ ang,
    const float* __restrict__ b0B, const float* __restrict__ b0A,
    const float* __restrict__ W1,
    const float* __restrict__ Wc2, const float* __restrict__ W1e2,
    const float* __restrict__ Wcc,
    const float* __restrict__ wa3, const float* __restrict__ wg3,
    const float* __restrict__ ccv,
    float* __restrict__ out, double* __restrict__ lossp)
{
    extern __shared__ float sm[];
    float* W1S = sm + EF_W1;     // [128][136] tf32
    float* HD1 = sm + EF_HD1;    // [64][132] tf32
    float* HS1 = sm + EF_HS1;    // [64][132] fp32
    float* W12S = sm + EF_W12;   // 128 x 12 (9 used) skewed
    float* B0A = sm + EF_B0A;
    float* B0B = sm + EF_B0B;
    float* WA3 = sm + EF_WA3;
    float* WG3 = sm + EF_WG3;
    float* CCV = sm + EF_CCV;
    int* SP = (int*)(sm + EF_SPI);
    int* DP = (int*)(sm + EF_DPI);
    float* RED = sm + EF_RED;
    const int tid = threadIdx.x;

    // stage weights once
    for (int i = tid; i < 16384; i += 512) {
        int k = i >> 7, n = i & 127;
        W1S[k * 136 + n] = __uint_as_float(tf32_bits(W1[i]));
    }
    for (int i = tid; i < 1152; i += 512) {
        int k = i / 9, c = i % 9;
        float v = (c < 3) ? Wc2[k * 3 + c]
                : (c < 6) ? W1e2[k * 3 + (c - 3)]
                          : Wcc[k * 3 + (c - 6)];
        W12S[W12(k) + c] = v;
    }
    if (tid < 32) ((float4*)B0A)[tid] = ((const float4*)b0A)[tid];
    else if (tid < 64) ((float4*)B0B)[tid - 32] = ((const float4*)b0B)[tid - 32];
    if (tid < 3) { WA3[tid] = wa3[tid]; WG3[tid] = wg3[tid]; CCV[tid] = ccv[tid]; }

    const int w = tid >> 5, lane = tid & 31;
    const int group = w >> 3;                 // 0: matvec warps, 1: MMA warps
    const int wi = w & 7, gid = lane >> 2, tig = lane & 3;
    const int m0 = (wi & 3) * 16, n0 = (wi >> 2) * 64;
    const int p = (tid & 255) >> 2, q = tid & 3;
    float lsum = 0.f;

    for (int tile = blockIdx.x; tile < EF_NTILE; tile += gridDim.x) {
        const int pbase = tile * 64;
        __syncthreads();   // previous tile fully consumed
        if (tid < 64) {
            SP[tid] = ei[pbase + tid];
            DP[tid] = ei[NP + pbase + tid];
        }
        __syncthreads();

        // build HS1 / HD1 from fp16 PB (all 512 threads)
#pragma unroll
        for (int it = 0; it < 4; it++) {
            int idx = tid + it * 512;
            int r = idx >> 5, c4 = idx & 31;
            int s = SP[r], d = DP[r];
            const uint2* Ps = (const uint2*)(PB + (size_t)s * 256);   // 64 x 4-half chunks
            const uint2* Pd = (const uint2*)(PB + (size_t)d * 256);
            float a1x, a1y, a1z, a1w, b1x, b1y, b1z, b1w;
            float a2x, a2y, a2z, a2w, b2x, b2y, b2z, b2w;
            h4_to_f4(__ldg(Ps + c4),      a1x, a1y, a1z, a1w);
            h4_to_f4(__ldg(Pd + 32 + c4), b1x, b1y, b1z, b1w);
            h4_to_f4(__ldg(Pd + c4),      a2x, a2y, a2z, a2w);
            h4_to_f4(__ldg(Ps + 32 + c4), b2x, b2y, b2z, b2w);
            float4 b0v = *(const float4*)&B0B[c4 * 4];
            float h1, h2;
            float4 hs, hd;
            h1 = lrelu(a1x + b1x + b0v.x); h2 = lrelu(a2x + b2x + b0v.x);
            hs.x = h1 + h2; hd.x = __uint_as_float(tf32_bits(h1 - h2));
            h1 = lrelu(a1y + b1y + b0v.y); h2 = lrelu(a2y + b2y + b0v.y);
            hs.y = h1 + h2; hd.y = __uint_as_float(tf32_bits(h1 - h2));
            h1 = lrelu(a1z + b1z + b0v.z); h2 = lrelu(a2z + b2z + b0v.z);
            hs.z = h1 + h2; hd.z = __uint_as_float(tf32_bits(h1 - h2));
            h1 = lrelu(a1w + b1w + b0v.w); h2 = lrelu(a2w + b2w + b0v.w);
            hs.w = h1 + h2; hd.w = __uint_as_float(tf32_bits(h1 - h2));
            *(float4*)&HS1[r * 132 + c4 * 4] = hs;
            *(float4*)&HD1[r * 132 + c4 * 4] = hd;
        }
        __syncthreads();

        if (group == 1) {
            // loss1 GEMM: HD1[64,128] @ W1[128,128], square-sum
            float c[8][4];
#pragma unroll
            for (int nt = 0; nt < 8; nt++)
#pragma unroll
                for (int j = 0; j < 4; j++) c[nt][j] = 0.f;
#pragma unroll 4
            for (int ks = 0; ks < 16; ks++) {
                int k = ks * 8;
                unsigned a0 = __float_as_uint(HD1[(m0 + gid) * 132 + k + tig]);
                unsigned a1 = __float_as_uint(HD1[(m0 + 8 + gid) * 132 + k + tig]);
                unsigned a2 = __float_as_uint(HD1[(m0 + gid) * 132 + k + 4 + tig]);
                unsigned a3 = __float_as_uint(HD1[(m0 + 8 + gid) * 132 + k + 4 + tig]);
#pragma unroll
                for (int nt = 0; nt < 8; nt++) {
                    unsigned b0f = __float_as_uint(W1S[(k + tig) * 136 + n0 + nt * 8 + gid]);
                    unsigned b1f = __float_as_uint(W1S[(k + 4 + tig) * 136 + n0 + nt * 8 + gid]);
                    mma_tf32(c[nt], a0, a1, a2, a3, b0f, b1f);
                }
            }
#pragma unroll
            for (int nt = 0; nt < 8; nt++)
#pragma unroll
                for (int j = 0; j < 4; j++) lsum += c[nt][j] * c[nt][j];
        } else {
            // per-pair matvec path (fp16 PA2 gathers)
            const int gp = pbase + p;
            const int s = SP[p], d = DP[p];
            const uint2* Ps = (const uint2*)(PA2 + (size_t)s * 256);
            const uint2* Pd = (const uint2*)(PA2 + (size_t)d * 256);
            float o0 = 0.f, o1 = 0.f, o2 = 0.f, t0 = 0.f, t1 = 0.f, t2 = 0.f;
#pragma unroll
            for (int c8 = 0; c8 < 8; c8++) {
                int c4 = q * 8 + c8;
                float av1[4], bv1[4], av2[4], bv2[4];
                h4_to_f4(__ldg(Ps + c4),      av1[0], av1[1], av1[2], av1[3]);
                h4_to_f4(__ldg(Pd + 32 + c4), bv1[0], bv1[1], bv1[2], bv1[3]);
                h4_to_f4(__ldg(Pd + c4),      av2[0], av2[1], av2[2], av2[3]);
                h4_to_f4(__ldg(Ps + 32 + c4), bv2[0], bv2[1], bv2[2], bv2[3]);
                float4 hv = *(const float4*)&HS1[p * 132 + c4 * 4];
                float4 b0v = *(const float4*)&B0A[c4 * 4];
                float hsv[4] = {hv.x, hv.y, hv.z, hv.w};
                float b0a[4] = {b0v.x, b0v.y, b0v.z, b0v.w};
#pragma unroll
                for (int j = 0; j < 4; j++) {
                    int k = c4 * 4 + j;
                    float h1 = lrelu(av1[j] + bv1[j] + b0a[j]);
                    float h2 = lrelu(av2[j] + bv2[j] + b0a[j]);
                    float hs = h1 + h2, hd = h1 - h2, f = hsv[j];
                    const float* wv = &W12S[W12(k)];
                    o0 += hs * wv[0] + f * wv[6];
                    o1 += hs * wv[1] + f * wv[7];
                    o2 += hs * wv[2] + f * wv[8];
                    t0 += hd * wv[3];
                    t1 += hd * wv[4];
                    t2 += hd * wv[5];
                }
            }
#pragma unroll
            for (int off = 2; off > 0; off >>= 1) {
                o0 += __shfl_down_sync(0xffffffffu, o0, off, 4);
                o1 += __shfl_down_sync(0xffffffffu, o1, off, 4);
                o2 += __shfl_down_sync(0xffffffffu, o2, off, 4);
                t0 += __shfl_down_sync(0xffffffffu, t0, off, 4);
                t1 += __shfl_down_sync(0xffffffffu, t1, off, 4);
                t2 += __shfl_down_sync(0xffffffffu, t2, off, 4);
            }
            if (q == 0) {
                float av = __ldg(act + gp), gv = __ldg(ang + gp);
                out[(size_t)gp * 3 + 0] = o0 + av * WA3[0] + gv * WG3[0] + CCV[0];
                out[(size_t)gp * 3 + 1] = o1 + av * WA3[1] + gv * WG3[1] + CCV[1];
                out[(size_t)gp * 3 + 2] = o2 + av * WA3[2] + gv * WG3[2] + CCV[2];
                lsum += t0 * t0 + t1 * t1 + t2 * t2;
            }
        }
    }

    // final loss reduce: warps 0-7 hold loss2, warps 8-15 hold loss1
#pragma unroll
    for (int o = 16; o > 0; o >>= 1) lsum += __shfl_down_sync(0xffffffffu, lsum, o);
    __syncthreads();
    if (lane == 0) RED[w] = lsum;
    __syncthreads();
    if (tid == 0) {
        float l2 = 0.f, l1 = 0.f;
#pragma unroll
        for (int ww = 0; ww < 8; ww++)  l2 += RED[ww];
#pragma unroll
        for (int ww = 8; ww < 16; ww++) l1 += RED[ww];
        atomicAdd(&lossp[0], (double)l1);
        atomicAdd(&lossp[1], (double)l2);
    }
}

// ------------------------------------------------------------------
__global__ void finalize_kernel(float* __restrict__ out, int idx)
{
    double l = 0.5 * (g_loss[0] / (800000.0 * 128.0) + g_loss[1] / (800000.0 * 3.0));
    out[idx] = (float)l;
}

// ------------------------------------------------------------------
extern "C" void kernel_launch(void* const* d_in, const int* in_sizes, int n_in,
                              void* d_out, int out_size)
{
    (void)in_sizes; (void)n_in;
    const float* xnf  = (const float*)d_in[0];
    const int*   ei   = (const int*)d_in[1];
    const float* ang  = (const float*)d_in[2];
    const float* act  = (const float*)d_in[3];
    const float* nc1W0 = (const float*)d_in[5];
    const float* nc1b0 = (const float*)d_in[6];
    const float* nc1W1 = (const float*)d_in[7];
    const float* nc1b1 = (const float*)d_in[8];
    const float* ec1W0 = (const float*)d_in[9];
    const float* ec1b0 = (const float*)d_in[10];
    const float* ec1W1 = (const float*)d_in[11];
    const float* ec1b1 = (const float*)d_in[12];
    const float* ec1Wl = (const float*)d_in[13];
    const float* ec1bl = (const float*)d_in[14];
    const float* nc2W0 = (const float*)d_in[15];
    const float* nc2b0 = (const float*)d_in[16];
    const float* nc2W1 = (const float*)d_in[17];
    const float* nc2b1 = (const float*)d_in[18];
    const float* ec2W0 = (const float*)d_in[19];
    const float* ec2b0 = (const float*)d_in[20];
    const float* ec2W1 = (const float*)d_in[21];
    const float* ec2b1 = (const float*)d_in[22];
    const float* ec2Wl = (const float*)d_in[23];
    const float* ec2bl = (const float*)d_in[24];
    float* out = (float*)d_out;

    float *hagg, *x1, *x2, *PA, *PB, *Wc, *c0, *Wc2, *c2, *Wcc, *wa3, *wg3, *cc;
    int *cnt, *offs, *cur, *srcs;
    double* loss;
    cudaGetSymbolAddress((void**)&hagg, g_hagg);
    cudaGetSymbolAddress((void**)&x1,   g_x1);
    cudaGetSymbolAddress((void**)&x2,   g_x2);
    cudaGetSymbolAddress((void**)&PA,   g_PA);
    cudaGetSymbolAddress((void**)&PB,   g_PB);
    cudaGetSymbolAddress((void**)&Wc,   g_Wc);
    cudaGetSymbolAddress((void**)&c0,   g_c0);
    cudaGetSymbolAddress((void**)&Wc2,  g_Wc2);
    cudaGetSymbolAddress((void**)&c2,   g_c2);
    cudaGetSymbolAddress((void**)&Wcc,  g_Wcc);
    cudaGetSymbolAddress((void**)&wa3,  g_wa3);
    cudaGetSymbolAddress((void**)&wg3,  g_wg3);
    cudaGetSymbolAddress((void**)&cc,   g_cc);
    cudaGetSymbolAddress((void**)&cnt,  g_cnt);
    cudaGetSymbolAddress((void**)&offs, g_offs);
    cudaGetSymbolAddress((void**)&cur,  g_cur);
    cudaGetSymbolAddress((void**)&srcs, g_srcs);
    cudaGetSymbolAddress((void**)&loss, g_loss);

    // Set the smem attribute ONCE, outside graph capture (first call is the
    // pre-capture correctness run). Calling it during capture kills the run.
    static int attr_done = 0;
    if (!attr_done) {
        cudaFuncSetAttribute(edge_fused_kernel,
                             cudaFuncAttributeMaxDynamicSharedMemorySize,
                             EF_TOT * sizeof(float));
        attr_done = 1;
    }

    cudaMemsetAsync(cnt, 0, (size_t)NN * sizeof(int));
    cudaMemsetAsync(cur, 0, (size_t)NN * sizeof(int));
    cudaMemsetAsync(loss, 0, 2 * sizeof(double));

    const int NB64 = (NN + 63) / 64;
    const int NAGG = (NN + 7) / 8;

    // CSR build
    count_kernel<<<(NE + 255) / 256, 256>>>(ei, cnt);
    scan_kernel<<<1, 1024>>>(cnt, offs);
    fill_kernel<<<(NE + 255) / 256, 256>>>(ei, offs, cur, srcs);

    // weight fusions
    fuseA_kernel<<<64, 256>>>(ec1W1, ec1Wl, Wc);
    fuseA2_kernel<<<1, 128>>>(ec1Wl, ec1b1, ec1bl, c0);
    fuseB_kernel<<<1, 384>>>(ec2W1, ec2Wl, ec2b1, ec2bl, Wc2, c2);
    fuseC_kernel<<<1, 384>>>(Wc, c0, ec1Wl, ec2Wl, c2, Wcc, wa3, wg3, cc);

    // ---- conv layer 1 (node) ----
    node_proj_kernel<false><<<NB64, 256>>>(xnf, nc1W0, PA);
    aggregate_kernel<<<NAGG, 256>>>(PA, offs, srcs, nc1b0, hagg);
    node_gemm_kernel<<<NB64, 256>>>(hagg, offs, nc1W1, nc1b1, x1);

    // ---- projection for edge conv 1 (fp16 table) ----
    node_proj_kernel<true><<<NB64, 256>>>(x1, ec1W0, PB);

    // ---- conv layer 2 (node) ----
    node_proj_kernel<false><<<NB64, 256>>>(x1, nc2W0, PA);
    aggregate_kernel<<<NAGG, 256>>>(PA, offs, srcs, nc2b0, hagg);
    node_gemm_kernel<<<NB64, 256>>>(hagg, offs, nc2W1, nc2b1, x2);

    // ---- projection for edge conv 2 (fp16 table, reuses g_PA) ----
    node_proj_kernel<true><<<NB64, 256>>>(x2, ec2W0, PA);

    // ---- merged edge convs ----
    edge_fused_kernel<<<148, 512, EF_TOT * sizeof(float)>>>(
        (const __half*)PB, (const __half*)PA, ei, act, ang, ec1b0, ec2b0, ec1W1,
        Wc2, ec2W1, Wcc, wa3, wg3, cc, out, loss);

    finalize_kernel<<<1, 1>>>(out, out_size - 1);
}